// round 1
// baseline (speedup 1.0000x reference)
#include <cuda_runtime.h>
#include <cstdint>
#include <cstddef>

// Problem constants (shapes fixed by the reference)
#define NM 50000
#define EM 800000
#define D0 64      // input feature dim
#define D1 128
#define D2 256
#define D3 512     // final dim
#define ODIM 128

// ---------------- device scratch (static; no allocation allowed) ------------
__device__ float g_h1[(size_t)NM * D1];            // 25.6 MB
__device__ float g_h2[(size_t)NM * D2];            // 51.2 MB
__device__ float g_h3[(size_t)NM * D3];            // 102.4 MB
__device__ float g_Wt[D3 * ODIM];                  // W transposed [512,128]
__device__ int   g_src[EM];
__device__ int   g_dst[EM];
__device__ float g_din[NM];                        // becomes inv_in
__device__ float g_dout[NM];                       // becomes inv_out
__device__ int   g_flag32;                         // 1 if edge dtype is int32

// ---------------- helpers ---------------------------------------------------
__device__ __forceinline__ void red4(float* p, float a, float b, float c, float d) {
    asm volatile("red.global.add.v4.f32 [%0], {%1,%2,%3,%4};"
                 :: "l"(p), "f"(a), "f"(b), "f"(c), "f"(d) : "memory");
}

// ---------------- setup kernels ---------------------------------------------
__global__ void init_small_kernel(int n) {
    int i = blockIdx.x * blockDim.x + threadIdx.x;
    if (i < n) { g_din[i] = 0.f; g_dout[i] = 0.f; }
    if (i == 0) g_flag32 = 0;
}

// If data is int64, every odd 32-bit word in the first 2*E words is a zero
// high-half (values in [0, 50000)). If int32, odd words are real indices.
__global__ void detect_kernel(const unsigned* __restrict__ p, int n32) {
    int i = blockIdx.x * blockDim.x + threadIdx.x;
    int idx = 2 * i + 1;
    if (idx < n32 && p[idx] != 0u) g_flag32 = 1;
}

__global__ void convert_kernel(const void* __restrict__ e, int E) {
    int i = blockIdx.x * blockDim.x + threadIdx.x;
    if (i >= E) return;
    if (g_flag32) {
        const int* p = (const int*)e;
        g_src[i] = p[i]; g_dst[i] = p[E + i];
    } else {
        const long long* p = (const long long*)e;
        g_src[i] = (int)p[i]; g_dst[i] = (int)p[E + i];
    }
}

__global__ void zero_state_kernel(size_t n1, size_t n2, size_t n3) { // counts in float4
    size_t i = (size_t)blockIdx.x * blockDim.x + threadIdx.x;
    float4 z = make_float4(0.f, 0.f, 0.f, 0.f);
    if (i < n1) ((float4*)g_h1)[i] = z;
    if (i < n2) ((float4*)g_h2)[i] = z;
    if (i < n3) ((float4*)g_h3)[i] = z;
}

__global__ void degree_kernel(int E) {
    int i = blockIdx.x * blockDim.x + threadIdx.x;
    if (i < E) {
        atomicAdd(&g_din[g_dst[i]], 1.f);
        atomicAdd(&g_dout[g_src[i]], 1.f);
    }
}

__global__ void inv_kernel(int n) {
    int i = blockIdx.x * blockDim.x + threadIdx.x;
    if (i < n) {
        g_din[i]  = 1.f / fmaxf(g_din[i], 1.f);
        g_dout[i] = 1.f / fmaxf(g_dout[i], 1.f);
    }
}

// ---------------- aggregation: one hop, both directions ---------------------
// hn[v, 0:D)   += h[src]*inv_in[v]  for edges with dst==v
// hn[v, D:2D)  += h[dst]*inv_out[v] for edges with src==v
template <int D>
__global__ void __launch_bounds__(256) agg_kernel(
    const float* __restrict__ h, float* __restrict__ hn, int E)
{
    constexpr int C = D / 4;                 // float4 chunks per row
    unsigned total = (unsigned)E * C;
    unsigned i = blockIdx.x * blockDim.x + threadIdx.x;
    if (i >= total) return;
    int e = i / C;
    int c = i % C;
    int s = g_src[e];
    int d = g_dst[e];
    float4 hs = __ldg((const float4*)(h + (size_t)s * D) + c);
    float4 hd = __ldg((const float4*)(h + (size_t)d * D) + c);
    float wi = __ldg(&g_din[d]);
    float wo = __ldg(&g_dout[s]);
    float* pd = hn + (size_t)d * (2 * D) + c * 4;
    float* ps = hn + (size_t)s * (2 * D) + D + c * 4;
    red4(pd, hs.x * wi, hs.y * wi, hs.z * wi, hs.w * wi);
    red4(ps, hd.x * wo, hd.y * wo, hd.z * wo, hd.w * wo);
}

// ---------------- W transpose + GEMM ----------------------------------------
__global__ void transpose_w_kernel(const float* __restrict__ W) { // [128,512] -> [512,128]
    int i = blockIdx.x * blockDim.x + threadIdx.x;
    if (i < ODIM * D3) {
        int o = i / D3, k = i % D3;
        g_Wt[k * ODIM + o] = W[i];
    }
}

// C[N,128] = A[N,512] @ Wt[512,128] + bias ; tile 64x128x32, 256 threads,
// per-thread 4x8 micro-tile.
__global__ void __launch_bounds__(256) gemm_kernel(
    const float* __restrict__ A, const float* __restrict__ bias,
    float* __restrict__ C, int N)
{
    __shared__ float As[32][64];    // [k][m]
    __shared__ float Bs[32][128];   // [k][n]
    int tid = threadIdx.x;
    int blockRow = blockIdx.x * 64;
    int ry = tid >> 4;              // 0..15 -> rows ry*4..+3
    int cx = tid & 15;              // 0..15 -> cols cx*8..+7
    float acc[4][8] = {};

    for (int k0 = 0; k0 < D3; k0 += 32) {
        #pragma unroll
        for (int q = 0; q < 2; q++) {           // A tile: 512 float4, 2/thread
            int idx = tid + q * 256;
            int m  = idx >> 3;
            int k4 = idx & 7;
            int row = blockRow + m;
            float4 v = make_float4(0.f, 0.f, 0.f, 0.f);
            if (row < N)
                v = __ldg((const float4*)(A + (size_t)row * D3 + k0) + k4);
            As[k4 * 4 + 0][m] = v.x;
            As[k4 * 4 + 1][m] = v.y;
            As[k4 * 4 + 2][m] = v.z;
            As[k4 * 4 + 3][m] = v.w;
        }
        #pragma unroll
        for (int q = 0; q < 4; q++) {           // B tile: 1024 float4, 4/thread
            int idx = tid + q * 256;
            int kk = idx >> 5;
            int n4 = idx & 31;
            float4 v = __ldg((const float4*)(g_Wt + (size_t)(k0 + kk) * ODIM) + n4);
            *(float4*)&Bs[kk][n4 * 4] = v;
        }
        __syncthreads();
        #pragma unroll
        for (int kk = 0; kk < 32; kk++) {
            float a[4], bb[8];
            #pragma unroll
            for (int i = 0; i < 4; i++) a[i] = As[kk][ry * 4 + i];
            #pragma unroll
            for (int j = 0; j < 8; j++) bb[j] = Bs[kk][cx * 8 + j];
            #pragma unroll
            for (int i = 0; i < 4; i++)
                #pragma unroll
                for (int j = 0; j < 8; j++)
                    acc[i][j] += a[i] * bb[j];
        }
        __syncthreads();
    }

    #pragma unroll
    for (int i = 0; i < 4; i++) {
        int row = blockRow + ry * 4 + i;
        if (row < N) {
            #pragma unroll
            for (int j = 0; j < 8; j++) {
                int col = cx * 8 + j;
                C[(size_t)row * ODIM + col] = acc[i][j] + __ldg(&bias[col]);
            }
        }
    }
}

// ---------------- launch ----------------------------------------------------
extern "C" void kernel_launch(void* const* d_in, const int* in_sizes, int n_in,
                              void* d_out, int out_size)
{
    const float* feat  = (const float*)d_in[0];
    const void*  edges = d_in[1];
    const float* W     = (const float*)d_in[2];
    const float* bias  = (const float*)d_in[3];
    float* out = (float*)d_out;

    int N = in_sizes[0] / D0;     // 50000
    int E = in_sizes[1] / 2;      // 800000

    float *h1, *h2, *h3;
    cudaGetSymbolAddress((void**)&h1, g_h1);
    cudaGetSymbolAddress((void**)&h2, g_h2);
    cudaGetSymbolAddress((void**)&h3, g_h3);

    const int T = 256;
    init_small_kernel<<<(N + T - 1) / T, T>>>(N);
    detect_kernel<<<(E + T - 1) / T, T>>>((const unsigned*)edges, 2 * E);
    convert_kernel<<<(E + T - 1) / T, T>>>(edges, E);

    size_t n1 = (size_t)N * D1 / 4, n2 = (size_t)N * D2 / 4, n3 = (size_t)N * D3 / 4;
    zero_state_kernel<<<(unsigned)((n3 + T - 1) / T), T>>>(n1, n2, n3);

    degree_kernel<<<(E + T - 1) / T, T>>>(E);
    inv_kernel<<<(N + T - 1) / T, T>>>(N);

    unsigned t1 = (unsigned)E * (D0 / 4);
    unsigned t2 = (unsigned)E * (D1 / 4);
    unsigned t3 = (unsigned)E * (D2 / 4);
    agg_kernel<D0><<<(t1 + T - 1) / T, T>>>(feat, h1, E);
    agg_kernel<D1><<<(t2 + T - 1) / T, T>>>(h1,  h2, E);
    agg_kernel<D2><<<(t3 + T - 1) / T, T>>>(h2,  h3, E);

    transpose_w_kernel<<<(ODIM * D3 + T - 1) / T, T>>>(W);
    gemm_kernel<<<(N + 63) / 64, T>>>(h3, bias, out, N);
}

// round 3
// speedup vs baseline: 2.4303x; 2.4303x over previous
#include <cuda_runtime.h>
#include <cstdint>
#include <cstddef>

#define NM 50000
#define EM 800000
#define D0 64
#define D1 128
#define D2 256
#define ODIM 128
#define NB ((NM + 1023) / 1024)   // scan blocks per direction = 49

// ---------------- device scratch ------------------------------------------
__device__ float g_h1[(size_t)NM * D1];      // 25.6 MB
__device__ float g_h2[(size_t)NM * D2];      // 51.2 MB
__device__ float g_P [(size_t)NM * D2];      // 51.2 MB  (Pin cols 0-127, Pout 128-255)
__device__ float g_Wt2[D2 * D2];             // 256x256 rearranged weights
__device__ int   g_src[EM];
__device__ int   g_dst[EM];
__device__ int   g_adj[2][EM];               // [0]=in-adjacency (srcs per dst), [1]=out
__device__ int   g_cnt[2][NM];               // degrees
__device__ int   g_rowptr[2][NM];
__device__ int   g_cursor[2][NM];
__device__ float g_inv[2][NM];
__device__ int   g_part[2][64];
__device__ int   g_flag32;

// ---------------- setup ----------------------------------------------------
__global__ void init_kernel(int n) {
    int i = blockIdx.x * blockDim.x + threadIdx.x;
    if (i < n) { g_cnt[0][i] = 0; g_cnt[1][i] = 0; }
    if (i == 0) g_flag32 = 0;
}

// int64 values < 50000 -> all odd 32-bit words of first 2E words are zero.
__global__ void detect_kernel(const unsigned* __restrict__ p, int n32) {
    int i = blockIdx.x * blockDim.x + threadIdx.x;
    int idx = 2 * i + 1;
    if (idx < n32 && p[idx] != 0u) g_flag32 = 1;
}

__global__ void convert_count_kernel(const void* __restrict__ e, int E) {
    int i = blockIdx.x * blockDim.x + threadIdx.x;
    if (i >= E) return;
    int s, d;
    if (g_flag32) {
        const int* p = (const int*)e;
        s = p[i]; d = p[E + i];
    } else {
        const long long* p = (const long long*)e;
        s = (int)p[i]; d = (int)p[E + i];
    }
    g_src[i] = s; g_dst[i] = d;
    atomicAdd(&g_cnt[0][d], 1);   // in-degree of d
    atomicAdd(&g_cnt[1][s], 1);   // out-degree of s
}

// ---------------- hierarchical exclusive scan ------------------------------
__global__ void scan1_kernel(int n) {
    int dir = blockIdx.y;
    int tid = threadIdx.x;
    int i = blockIdx.x * 1024 + tid;
    int v = (i < n) ? g_cnt[dir][i] : 0;
    int lane = tid & 31, w = tid >> 5;
    int x = v;
    #pragma unroll
    for (int o = 1; o < 32; o <<= 1) {
        int y = __shfl_up_sync(0xffffffffu, x, o);
        if (lane >= o) x += y;
    }
    __shared__ int ws[32];
    if (lane == 31) ws[w] = x;
    __syncthreads();
    if (w == 0) {
        int y = ws[lane];
        #pragma unroll
        for (int o = 1; o < 32; o <<= 1) {
            int z = __shfl_up_sync(0xffffffffu, y, o);
            if (lane >= o) y += z;
        }
        ws[lane] = y;
    }
    __syncthreads();
    int excl = x - v + (w ? ws[w - 1] : 0);
    if (i < n) g_rowptr[dir][i] = excl;
    if (tid == 0) g_part[dir][blockIdx.x] = ws[31];
}

__global__ void scan2_kernel() {   // 2 threads, serial per direction (49 elems)
    int dir = threadIdx.x;
    if (dir < 2) {
        int acc = 0;
        for (int b = 0; b < NB; b++) {
            int t = g_part[dir][b];
            g_part[dir][b] = acc;
            acc += t;
        }
    }
}

__global__ void scan3_kernel(int n) {
    int dir = blockIdx.y;
    int i = blockIdx.x * 1024 + threadIdx.x;
    if (i < n) {
        int v = g_rowptr[dir][i] + g_part[dir][blockIdx.x];
        g_rowptr[dir][i] = v;
        g_cursor[dir][i] = v;
        g_inv[dir][i] = 1.0f / fmaxf((float)g_cnt[dir][i], 1.0f);
    }
}

__global__ void fill_kernel(int E) {
    int i = blockIdx.x * blockDim.x + threadIdx.x;
    if (i >= E) return;
    int s = g_src[i], d = g_dst[i];
    int p = atomicAdd(&g_cursor[0][d], 1);
    g_adj[0][p] = s;
    int q = atomicAdd(&g_cursor[1][s], 1);
    g_adj[1][q] = d;
}

// ---------------- CSR aggregation: out[v, dir*D .. +D) = inv*sum h[u] ------
template <int D>
__global__ void __launch_bounds__(256) agg_kernel(
    const float* __restrict__ h, float* __restrict__ out, int ostride, int n)
{
    constexpr int L = D / 4;                       // lanes per node
    int gid = blockIdx.x * blockDim.x + threadIdx.x;
    int node = gid / L;
    int lane = gid % L;
    int dir = blockIdx.y;
    if (node >= n) return;
    int start = g_rowptr[dir][node];
    int deg   = g_cnt[dir][node];
    const int* adj = g_adj[dir];
    float4 acc = make_float4(0.f, 0.f, 0.f, 0.f);
    for (int t = 0; t < deg; t++) {
        int u = __ldg(&adj[start + t]);
        float4 v = __ldg((const float4*)(h + (size_t)u * D) + lane);
        acc.x += v.x; acc.y += v.y; acc.z += v.z; acc.w += v.w;
    }
    float w = g_inv[dir][node];
    float4 r = make_float4(acc.x * w, acc.y * w, acc.z * w, acc.w * w);
    ((float4*)(out + (size_t)node * ostride + dir * D))[lane] = r;
}

// ---------------- fused final hop: aggregate P, scale, add bias ------------
__global__ void __launch_bounds__(256) hop3_kernel(
    const float* __restrict__ P, const float* __restrict__ bias,
    float* __restrict__ out, int n)
{
    int node = blockIdx.x * 8 + (threadIdx.x >> 5);
    int lane = threadIdx.x & 31;
    if (node >= n) return;
    float4 aI = make_float4(0.f, 0.f, 0.f, 0.f);
    float4 aO = make_float4(0.f, 0.f, 0.f, 0.f);
    int s0 = g_rowptr[0][node], d0 = g_cnt[0][node];
    for (int t = 0; t < d0; t++) {
        int u = __ldg(&g_adj[0][s0 + t]);
        float4 v = __ldg((const float4*)(P + (size_t)u * D2) + lane);
        aI.x += v.x; aI.y += v.y; aI.z += v.z; aI.w += v.w;
    }
    int s1 = g_rowptr[1][node], d1 = g_cnt[1][node];
    for (int t = 0; t < d1; t++) {
        int u = __ldg(&g_adj[1][s1 + t]);
        float4 v = __ldg((const float4*)(P + (size_t)u * D2 + ODIM) + lane);
        aO.x += v.x; aO.y += v.y; aO.z += v.z; aO.w += v.w;
    }
    float wi = g_inv[0][node], wo = g_inv[1][node];
    float4 b = __ldg((const float4*)bias + lane);
    float4 r;
    r.x = aI.x * wi + aO.x * wo + b.x;
    r.y = aI.y * wi + aO.y * wo + b.y;
    r.z = aI.z * wi + aO.z * wo + b.z;
    r.w = aI.w * wi + aO.w * wo + b.w;
    ((float4*)(out + (size_t)node * ODIM))[lane] = r;
}

// ---------------- weight rearrange + GEMM ----------------------------------
// Wt2[k][j] : j<128 -> W[j][k] ; j>=128 -> W[j-128][256+k]   (W is [128,512])
__global__ void build_w_kernel(const float* __restrict__ W) {
    int i = blockIdx.x * blockDim.x + threadIdx.x;
    if (i < D2 * D2) {
        int k = i / D2, j = i % D2;
        g_Wt2[i] = (j < ODIM) ? W[(size_t)j * 512 + k]
                              : W[(size_t)(j - ODIM) * 512 + 256 + k];
    }
}

// P[N,256] = h2[N,256] @ Wt2[256,256]; tile 128x128x32, 256 thr, 8x8 micro
__global__ void __launch_bounds__(256) gemm_kernel(
    const float* __restrict__ A, float* __restrict__ C, int N)
{
    __shared__ float As[32][128];
    __shared__ float Bs[32][128];
    int tid = threadIdx.x;
    int blockRow = blockIdx.x * 128;
    int blockCol = blockIdx.y * 128;
    int ty = tid >> 4;           // 0..15 -> rows ty*8..+7
    int tx = tid & 15;           // 0..15 -> cols tx*8..+7
    float acc[8][8] = {};

    for (int k0 = 0; k0 < D2; k0 += 32) {
        #pragma unroll
        for (int q = 0; q < 4; q++) {          // A: 128x32 = 1024 float4
            int idx = tid + q * 256;
            int m = idx >> 3;
            int k4 = idx & 7;
            int row = blockRow + m;
            float4 v = make_float4(0.f, 0.f, 0.f, 0.f);
            if (row < N)
                v = __ldg((const float4*)(A + (size_t)row * D2 + k0) + k4);
            As[k4 * 4 + 0][m] = v.x;
            As[k4 * 4 + 1][m] = v.y;
            As[k4 * 4 + 2][m] = v.z;
            As[k4 * 4 + 3][m] = v.w;
        }
        #pragma unroll
        for (int q = 0; q < 4; q++) {          // B: 32x128 = 1024 float4
            int idx = tid + q * 256;
            int kk = idx >> 5;
            int n4 = idx & 31;
            float4 v = __ldg((const float4*)(g_Wt2 + (size_t)(k0 + kk) * D2 + blockCol) + n4);
            *(float4*)&Bs[kk][n4 * 4] = v;
        }
        __syncthreads();
        #pragma unroll
        for (int kk = 0; kk < 32; kk++) {
            float a[8], b[8];
            #pragma unroll
            for (int i = 0; i < 8; i++) a[i] = As[kk][ty * 8 + i];
            #pragma unroll
            for (int j = 0; j < 8; j++) b[j] = Bs[kk][tx * 8 + j];
            #pragma unroll
            for (int i = 0; i < 8; i++)
                #pragma unroll
                for (int j = 0; j < 8; j++)
                    acc[i][j] += a[i] * b[j];
        }
        __syncthreads();
    }

    #pragma unroll
    for (int i = 0; i < 8; i++) {
        int row = blockRow + ty * 8 + i;
        if (row < N) {
            float* cp = C + (size_t)row * D2 + blockCol + tx * 8;
            #pragma unroll
            for (int j = 0; j < 8; j += 4)
                *(float4*)(cp + j) = make_float4(acc[i][j], acc[i][j+1], acc[i][j+2], acc[i][j+3]);
        }
    }
}

// ---------------- launch ----------------------------------------------------
extern "C" void kernel_launch(void* const* d_in, const int* in_sizes, int n_in,
                              void* d_out, int out_size)
{
    const float* feat  = (const float*)d_in[0];
    const void*  edges = d_in[1];
    const float* W     = (const float*)d_in[2];
    const float* bias  = (const float*)d_in[3];
    float* out = (float*)d_out;

    int N = in_sizes[0] / D0;     // 50000
    int E = in_sizes[1] / 2;      // 800000

    float *h1, *h2, *P;
    cudaGetSymbolAddress((void**)&h1, g_h1);
    cudaGetSymbolAddress((void**)&h2, g_h2);
    cudaGetSymbolAddress((void**)&P,  g_P);

    const int T = 256;
    init_kernel<<<(N + T - 1) / T, T>>>(N);
    detect_kernel<<<(E + T - 1) / T, T>>>((const unsigned*)edges, 2 * E);
    convert_count_kernel<<<(E + T - 1) / T, T>>>(edges, E);

    dim3 sgrid((N + 1023) / 1024, 2);
    scan1_kernel<<<sgrid, 1024>>>(N);
    scan2_kernel<<<1, 32>>>();
    scan3_kernel<<<sgrid, 1024>>>(N);
    fill_kernel<<<(E + T - 1) / T, T>>>(E);

    // hop1: feature (D=64) -> h1 [N,128]
    {
        unsigned total = (unsigned)N * (D0 / 4);
        dim3 g((total + T - 1) / T, 2);
        agg_kernel<D0><<<g, T>>>(feat, h1, D1, N);
    }
    // hop2: h1 (D=128) -> h2 [N,256]
    {
        unsigned total = (unsigned)N * (D1 / 4);
        dim3 g((total + T - 1) / T, 2);
        agg_kernel<D1><<<g, T>>>(h1, h2, D2, N);
    }
    // projection: P = h2 @ Wt2
    build_w_kernel<<<(D2 * D2 + T - 1) / T, T>>>(W);
    {
        dim3 g((N + 127) / 128, 2);
        gemm_kernel<<<g, T>>>(h2, P, N);
    }
    // fused hop3 + scale + bias -> out [N,128]
    hop3_kernel<<<(N + 7) / 8, T>>>(P, bias, out, N);
}

// round 5
// speedup vs baseline: 3.9163x; 1.6115x over previous
#include <cuda_runtime.h>
#include <cuda_fp16.h>
#include <cstdint>
#include <cstddef>

#define NM 50000
#define EM 800000
#define D0 64
#define D1 128
#define D2 256
#define ODIM 128
#define NB ((NM + 1023) / 1024)

// ---------------- device scratch ------------------------------------------
__device__ __half g_h1h[(size_t)NM * D1];    // 12.8 MB (fp16)
__device__ float  g_h2[(size_t)NM * D2];     // 51.2 MB (fp32, GEMM input)
__device__ __half g_Ph[(size_t)NM * D2];     // 25.6 MB (fp16; Pin 0-127, Pout 128-255)
__device__ float  g_Wt2[D2 * D2];
__device__ int    g_src[EM];
__device__ int    g_dst[EM];
__device__ int    g_adj[2][EM];
__device__ int    g_cnt[2][NM];
__device__ int    g_rowptr[2][NM];
__device__ int    g_cursor[2][NM];
__device__ float  g_inv[2][NM];
__device__ int    g_part[2][64];
__device__ int    g_flag32;

// ---------------- setup ----------------------------------------------------
__global__ void init_kernel(int n) {
    int i = blockIdx.x * blockDim.x + threadIdx.x;
    if (i < n) { g_cnt[0][i] = 0; g_cnt[1][i] = 0; }
    if (i == 0) g_flag32 = 0;
}

__global__ void detect_kernel(const unsigned* __restrict__ p, int n32) {
    int i = blockIdx.x * blockDim.x + threadIdx.x;
    int idx = 2 * i + 1;
    if (idx < n32 && p[idx] != 0u) g_flag32 = 1;
}

__global__ void convert_count_kernel(const void* __restrict__ e, int E) {
    int i = blockIdx.x * blockDim.x + threadIdx.x;
    if (i >= E) return;
    int s, d;
    if (g_flag32) {
        const int* p = (const int*)e;
        s = p[i]; d = p[E + i];
    } else {
        const long long* p = (const long long*)e;
        s = (int)p[i]; d = (int)p[E + i];
    }
    g_src[i] = s; g_dst[i] = d;
    atomicAdd(&g_cnt[0][d], 1);
    atomicAdd(&g_cnt[1][s], 1);
}

__global__ void scan1_kernel(int n) {
    int dir = blockIdx.y;
    int tid = threadIdx.x;
    int i = blockIdx.x * 1024 + tid;
    int v = (i < n) ? g_cnt[dir][i] : 0;
    int lane = tid & 31, w = tid >> 5;
    int x = v;
    #pragma unroll
    for (int o = 1; o < 32; o <<= 1) {
        int y = __shfl_up_sync(0xffffffffu, x, o);
        if (lane >= o) x += y;
    }
    __shared__ int ws[32];
    if (lane == 31) ws[w] = x;
    __syncthreads();
    if (w == 0) {
        int y = ws[lane];
        #pragma unroll
        for (int o = 1; o < 32; o <<= 1) {
            int z = __shfl_up_sync(0xffffffffu, y, o);
            if (lane >= o) y += z;
        }
        ws[lane] = y;
    }
    __syncthreads();
    int excl = x - v + (w ? ws[w - 1] : 0);
    if (i < n) g_rowptr[dir][i] = excl;
    if (tid == 0) g_part[dir][blockIdx.x] = ws[31];
}

__global__ void scan2_kernel() {
    int dir = threadIdx.x;
    if (dir < 2) {
        int acc = 0;
        for (int b = 0; b < NB; b++) {
            int t = g_part[dir][b];
            g_part[dir][b] = acc;
            acc += t;
        }
    }
}

__global__ void scan3_kernel(int n) {
    int dir = blockIdx.y;
    int i = blockIdx.x * 1024 + threadIdx.x;
    if (i < n) {
        int v = g_rowptr[dir][i] + g_part[dir][blockIdx.x];
        g_rowptr[dir][i] = v;
        g_cursor[dir][i] = v;
        g_inv[dir][i] = 1.0f / fmaxf((float)g_cnt[dir][i], 1.0f);
    }
}

__global__ void fill_kernel(int E) {
    int i = blockIdx.x * blockDim.x + threadIdx.x;
    if (i >= E) return;
    int s = g_src[i], d = g_dst[i];
    int p = atomicAdd(&g_cursor[0][d], 1);
    g_adj[0][p] = s;
    int q = atomicAdd(&g_cursor[1][s], 1);
    g_adj[1][q] = d;
}

// ---------------- hop1: feature fp32 (D=64) -> h1 fp16 [N,128] -------------
__global__ void __launch_bounds__(256) hop1_kernel(
    const float* __restrict__ feat, __half* __restrict__ h1, int n)
{
    int gid = blockIdx.x * blockDim.x + threadIdx.x;
    int node = gid >> 4;
    int lane = gid & 15;               // 16 lanes x float4 = 64
    int dir = blockIdx.y;
    if (node >= n) return;
    int start = g_rowptr[dir][node];
    int deg   = g_cnt[dir][node];
    const int* adj = g_adj[dir];
    float4 acc = make_float4(0.f, 0.f, 0.f, 0.f);
    for (int t = 0; t < deg; t++) {
        int u = __ldg(&adj[start + t]);
        float4 v = __ldg((const float4*)(feat + (size_t)u * D0) + lane);
        acc.x += v.x; acc.y += v.y; acc.z += v.z; acc.w += v.w;
    }
    float w = g_inv[dir][node];
    __half2 lo = __floats2half2_rn(acc.x * w, acc.y * w);
    __half2 hi = __floats2half2_rn(acc.z * w, acc.w * w);
    __half2* out = (__half2*)(h1 + (size_t)node * D1 + dir * D0 + lane * 4);
    out[0] = lo; out[1] = hi;
}

// ---------------- hop2: h1 fp16 (D=128) -> h2 fp32 [N,256] -----------------
__global__ void __launch_bounds__(256) hop2_kernel(
    const __half* __restrict__ h1, float* __restrict__ h2, int n)
{
    int gid = blockIdx.x * blockDim.x + threadIdx.x;
    int node = gid >> 4;
    int lane = gid & 15;               // 16 lanes x 8 halves = 128
    int dir = blockIdx.y;
    if (node >= n) return;
    int start = g_rowptr[dir][node];
    int deg   = g_cnt[dir][node];
    const int* adj = g_adj[dir];
    float acc[8] = {};
    for (int t = 0; t < deg; t++) {
        int u = __ldg(&adj[start + t]);
        uint4 r = __ldg((const uint4*)(h1 + (size_t)u * D1) + lane);
        const __half2* h = (const __half2*)&r;
        #pragma unroll
        for (int j = 0; j < 4; j++) {
            float2 f = __half22float2(h[j]);
            acc[2 * j]     += f.x;
            acc[2 * j + 1] += f.y;
        }
    }
    float w = g_inv[dir][node];
    float* out = h2 + (size_t)node * D2 + dir * D1 + lane * 8;
    #pragma unroll
    for (int j = 0; j < 8; j += 4)
        *(float4*)(out + j) = make_float4(acc[j] * w, acc[j+1] * w, acc[j+2] * w, acc[j+3] * w);
}

// ---------------- weight rearrange -----------------------------------------
// Wt2[k][j] : j<128 -> W[j][k] ; j>=128 -> W[j-128][256+k]   (W is [128,512])
__global__ void build_w_kernel(const float* __restrict__ W) {
    int i = blockIdx.x * blockDim.x + threadIdx.x;
    if (i < D2 * D2) {
        int k = i / D2, j = i % D2;
        g_Wt2[i] = (j < ODIM) ? W[(size_t)j * 512 + k]
                              : W[(size_t)(j - ODIM) * 512 + 256 + k];
    }
}

// ---------------- tf32 tensor-core GEMM: P = h2 @ Wt2, fp16 out ------------
__device__ __forceinline__ uint32_t f2tf(float f) {
    uint32_t u;
    asm("cvt.rna.tf32.f32 %0, %1;" : "=r"(u) : "f"(f));
    return u;
}

__device__ __forceinline__ void mma_tf32(float* c, const uint32_t* a,
                                         uint32_t b0, uint32_t b1) {
    asm volatile(
        "mma.sync.aligned.m16n8k8.row.col.f32.tf32.tf32.f32 "
        "{%0,%1,%2,%3}, {%4,%5,%6,%7}, {%8,%9}, {%0,%1,%2,%3};"
        : "+f"(c[0]), "+f"(c[1]), "+f"(c[2]), "+f"(c[3])
        : "r"(a[0]), "r"(a[1]), "r"(a[2]), "r"(a[3]), "r"(b0), "r"(b1));
}

__global__ void __launch_bounds__(256) gemm_tf32_kernel(
    const float* __restrict__ A, __half* __restrict__ C, int N)
{
    __shared__ float As[128][36];      // pad 36: mma LDS bank = lane
    __shared__ float Bs[32][132];      // pad 132: conflict-free
    int tid = threadIdx.x;
    int warp = tid >> 5, lane = tid & 31;
    int warpRow = warp >> 1;           // 0..3 (32 rows each)
    int warpCol = warp & 1;            // 0..1 (64 cols each)
    int g = lane >> 2, q = lane & 3;
    int blockRow = blockIdx.x * 128;
    int blockCol = blockIdx.y * 128;
    float c[2][8][4] = {};

    for (int k0 = 0; k0 < D2; k0 += 32) {
        #pragma unroll
        for (int i = 0; i < 4; i++) {          // A: 128x32 = 1024 float4
            int idx = tid + i * 256;
            int m = idx >> 3;
            int k4 = idx & 7;
            float4 v = make_float4(0.f, 0.f, 0.f, 0.f);
            int row = blockRow + m;
            if (row < N)
                v = __ldg((const float4*)(A + (size_t)row * D2 + k0) + k4);
            *(float4*)&As[m][k4 * 4] = v;
        }
        #pragma unroll
        for (int i = 0; i < 4; i++) {          // B: 32x128 = 1024 float4
            int idx = tid + i * 256;
            int kk = idx >> 5;
            int n4 = idx & 31;
            float4 v = __ldg((const float4*)(g_Wt2 + (size_t)(k0 + kk) * D2 + blockCol) + n4);
            *(float4*)&Bs[kk][n4 * 4] = v;
        }
        __syncthreads();
        #pragma unroll
        for (int ks = 0; ks < 4; ks++) {
            int kb = ks * 8;
            uint32_t a[2][4];
            #pragma unroll
            for (int mt = 0; mt < 2; mt++) {
                int rb = warpRow * 32 + mt * 16;
                a[mt][0] = f2tf(As[rb + g    ][kb + q    ]);
                a[mt][1] = f2tf(As[rb + g + 8][kb + q    ]);
                a[mt][2] = f2tf(As[rb + g    ][kb + q + 4]);
                a[mt][3] = f2tf(As[rb + g + 8][kb + q + 4]);
            }
            #pragma unroll
            for (int nt = 0; nt < 8; nt++) {
                int cb = warpCol * 64 + nt * 8 + g;
                uint32_t b0 = f2tf(Bs[kb + q    ][cb]);
                uint32_t b1 = f2tf(Bs[kb + q + 4][cb]);
                mma_tf32(c[0][nt], a[0], b0, b1);
                mma_tf32(c[1][nt], a[1], b0, b1);
            }
        }
        __syncthreads();
    }

    #pragma unroll
    for (int mt = 0; mt < 2; mt++)
        #pragma unroll
        for (int nt = 0; nt < 8; nt++) {
            int col = blockCol + warpCol * 64 + nt * 8 + q * 2;
            int r0 = blockRow + warpRow * 32 + mt * 16 + g;
            if (r0 < N)
                *(__half2*)(C + (size_t)r0 * D2 + col) =
                    __floats2half2_rn(c[mt][nt][0], c[mt][nt][1]);
            int r1 = r0 + 8;
            if (r1 < N)
                *(__half2*)(C + (size_t)r1 * D2 + col) =
                    __floats2half2_rn(c[mt][nt][2], c[mt][nt][3]);
        }
}

// ---------------- fused hop3: aggregate P fp16, scale, bias, out fp32 ------
__global__ void __launch_bounds__(256) hop3_kernel(
    const __half* __restrict__ P, const float* __restrict__ bias,
    float* __restrict__ out, int n)
{
    int node = blockIdx.x * 8 + (threadIdx.x >> 5);
    int lane = threadIdx.x & 31;       // 32 lanes x 4 halves = 128 per direction
    if (node >= n) return;
    float aI[4] = {}, aO[4] = {};
    int s0 = g_rowptr[0][node], d0 = g_cnt[0][node];
    for (int t = 0; t < d0; t++) {
        int u = __ldg(&g_adj[0][s0 + t]);
        uint2 r = __ldg((const uint2*)(P + (size_t)u * D2) + lane);
        float2 f0 = __half22float2(*(const __half2*)&r.x);
        float2 f1 = __half22float2(*(const __half2*)&r.y);
        aI[0] += f0.x; aI[1] += f0.y; aI[2] += f1.x; aI[3] += f1.y;
    }
    int s1 = g_rowptr[1][node], d1 = g_cnt[1][node];
    for (int t = 0; t < d1; t++) {
        int u = __ldg(&g_adj[1][s1 + t]);
        uint2 r = __ldg((const uint2*)(P + (size_t)u * D2 + ODIM) + lane);
        float2 f0 = __half22float2(*(const __half2*)&r.x);
        float2 f1 = __half22float2(*(const __half2*)&r.y);
        aO[0] += f0.x; aO[1] += f0.y; aO[2] += f1.x; aO[3] += f1.y;
    }
    float wi = g_inv[0][node], wo = g_inv[1][node];
    float4 b = __ldg((const float4*)bias + lane);
    float4 r;
    r.x = aI[0] * wi + aO[0] * wo + b.x;
    r.y = aI[1] * wi + aO[1] * wo + b.y;
    r.z = aI[2] * wi + aO[2] * wo + b.z;
    r.w = aI[3] * wi + aO[3] * wo + b.w;
    ((float4*)(out + (size_t)node * ODIM))[lane] = r;
}

// ---------------- launch ----------------------------------------------------
extern "C" void kernel_launch(void* const* d_in, const int* in_sizes, int n_in,
                              void* d_out, int out_size)
{
    const float* feat  = (const float*)d_in[0];
    const void*  edges = d_in[1];
    const float* W     = (const float*)d_in[2];
    const float* bias  = (const float*)d_in[3];
    float* out = (float*)d_out;

    int N = in_sizes[0] / D0;     // 50000
    int E = in_sizes[1] / 2;      // 800000

    __half *h1, *P;
    float *h2;
    cudaGetSymbolAddress((void**)&h1, g_h1h);
    cudaGetSymbolAddress((void**)&h2, g_h2);
    cudaGetSymbolAddress((void**)&P,  g_Ph);

    const int T = 256;
    init_kernel<<<(N + T - 1) / T, T>>>(N);
    detect_kernel<<<(E + T - 1) / T, T>>>((const unsigned*)edges, 2 * E);
    convert_count_kernel<<<(E + T - 1) / T, T>>>(edges, E);

    dim3 sgrid((N + 1023) / 1024, 2);
    scan1_kernel<<<sgrid, 1024>>>(N);
    scan2_kernel<<<1, 32>>>();
    scan3_kernel<<<sgrid, 1024>>>(N);
    fill_kernel<<<(E + T - 1) / T, T>>>(E);

    {
        unsigned total = (unsigned)N * 16;
        dim3 g((total + T - 1) / T, 2);
        hop1_kernel<<<g, T>>>(feat, h1, N);
    }
    {
        unsigned total = (unsigned)N * 16;
        dim3 g((total + T - 1) / T, 2);
        hop2_kernel<<<g, T>>>(h1, h2, N);
    }
    build_w_kernel<<<(D2 * D2 + T - 1) / T, T>>>(W);
    {
        dim3 g((N + 127) / 128, 2);
        gemm_tf32_kernel<<<g, T>>>(h2, P, N);
    }
    hop3_kernel<<<(N + 7) / 8, T>>>(P, bias, out, N);
}

// round 7
// speedup vs baseline: 4.1684x; 1.0644x over previous
#include <cuda_runtime.h>
#include <cuda_fp16.h>
#include <cstdint>
#include <cstddef>

#define NM 50000
#define EM 800000
#define D0 64
#define D1 128
#define D2 256
#define ODIM 128
#define NB ((NM + 1023) / 1024)

// ---------------- device scratch ------------------------------------------
__device__ __half g_feath[(size_t)NM * D0];  // 6.4 MB  fp16 features
__device__ __half g_h1h[(size_t)NM * D1];    // 12.8 MB fp16
__device__ float  g_h2[(size_t)NM * D2];     // 51.2 MB tf32-bit floats (GEMM A)
__device__ __half g_Ph[(size_t)NM * D2];     // 25.6 MB fp16 (Pin 0-127, Pout 128-255)
__device__ float  g_Wt2[D2 * D2];            // tf32-bit floats (GEMM B)
__device__ int    g_src[EM];
__device__ int    g_dst[EM];
__device__ int    g_adj[2][EM];
__device__ int    g_cnt[2][NM];
__device__ int    g_rowptr[2][NM];
__device__ int    g_cursor[2][NM];
__device__ float  g_inv[2][NM];
__device__ int    g_part[2][64];
__device__ int    g_flag32;

__device__ __forceinline__ uint32_t f2tf(float f) {
    uint32_t u;
    asm("cvt.rna.tf32.f32 %0, %1;" : "=r"(u) : "f"(f));
    return u;
}

// ---------------- setup: zero counts + flag + feature->fp16 ----------------
__global__ void initA_kernel(const float* __restrict__ feat, int n, int nfeat2) {
    int i = blockIdx.x * blockDim.x + threadIdx.x;
    if (i < n) { g_cnt[0][i] = 0; g_cnt[1][i] = 0; }
    if (i == 0) g_flag32 = 0;
    if (i < nfeat2) {
        float2 f = ((const float2*)feat)[i];
        ((__half2*)g_feath)[i] = __floats2half2_rn(f.x, f.y);
    }
}

__global__ void detect_kernel(const unsigned* __restrict__ p, int n32) {
    int i = blockIdx.x * blockDim.x + threadIdx.x;
    int idx = 2 * i + 1;
    if (idx < n32 && p[idx] != 0u) g_flag32 = 1;
}

__global__ void convert_count_kernel(const void* __restrict__ e, int E) {
    int i = blockIdx.x * blockDim.x + threadIdx.x;
    if (i >= E) return;
    int s, d;
    if (g_flag32) {
        const int* p = (const int*)e;
        s = p[i]; d = p[E + i];
    } else {
        const long long* p = (const long long*)e;
        s = (int)p[i]; d = (int)p[E + i];
    }
    g_src[i] = s; g_dst[i] = d;
    atomicAdd(&g_cnt[0][d], 1);
    atomicAdd(&g_cnt[1][s], 1);
}

// scan1 also folds the weight rearrange (tf32-converted)
__global__ void scan1_kernel(const float* __restrict__ W, int n) {
    // ---- build Wt2 (independent work on spare threads) ----
    int flat = (blockIdx.y * NB + blockIdx.x) * 1024 + threadIdx.x;
    if (flat < D2 * D2) {
        int k = flat / D2, j = flat % D2;
        float v = (j < ODIM) ? W[(size_t)j * 512 + k]
                             : W[(size_t)(j - ODIM) * 512 + 256 + k];
        g_Wt2[flat] = __uint_as_float(f2tf(v));
    }
    // ---- scan ----
    int dir = blockIdx.y;
    int tid = threadIdx.x;
    int i = blockIdx.x * 1024 + tid;
    int v = (i < n) ? g_cnt[dir][i] : 0;
    int lane = tid & 31, w = tid >> 5;
    int x = v;
    #pragma unroll
    for (int o = 1; o < 32; o <<= 1) {
        int y = __shfl_up_sync(0xffffffffu, x, o);
        if (lane >= o) x += y;
    }
    __shared__ int ws[32];
    if (lane == 31) ws[w] = x;
    __syncthreads();
    if (w == 0) {
        int y = ws[lane];
        #pragma unroll
        for (int o = 1; o < 32; o <<= 1) {
            int z = __shfl_up_sync(0xffffffffu, y, o);
            if (lane >= o) y += z;
        }
        ws[lane] = y;
    }
    __syncthreads();
    int excl = x - v + (w ? ws[w - 1] : 0);
    if (i < n) g_rowptr[dir][i] = excl;
    if (tid == 0) g_part[dir][blockIdx.x] = ws[31];
}

__global__ void scan2_kernel() {
    int dir = threadIdx.x;
    if (dir < 2) {
        int acc = 0;
        for (int b = 0; b < NB; b++) {
            int t = g_part[dir][b];
            g_part[dir][b] = acc;
            acc += t;
        }
    }
}

__global__ void scan3_kernel(int n) {
    int dir = blockIdx.y;
    int i = blockIdx.x * 1024 + threadIdx.x;
    if (i < n) {
        int v = g_rowptr[dir][i] + g_part[dir][blockIdx.x];
        g_rowptr[dir][i] = v;
        g_cursor[dir][i] = v;
        g_inv[dir][i] = 1.0f / fmaxf((float)g_cnt[dir][i], 1.0f);
    }
}

__global__ void fill_kernel(int E) {
    int i = blockIdx.x * blockDim.x + threadIdx.x;
    if (i >= E) return;
    int s = g_src[i], d = g_dst[i];
    int p = atomicAdd(&g_cursor[0][d], 1);
    g_adj[0][p] = s;
    int q = atomicAdd(&g_cursor[1][s], 1);
    g_adj[1][q] = d;
}

// ---------------- hop1: feat fp16 (D=64) -> h1 fp16 [N,128] ----------------
__global__ void __launch_bounds__(256) hop1_kernel(__half* __restrict__ h1, int n) {
    int gid = blockIdx.x * blockDim.x + threadIdx.x;
    int node = gid >> 4;
    int lane = gid & 15;               // 16 lanes x 4 halves = 64
    int dir = blockIdx.y;
    if (node >= n) return;
    int start = g_rowptr[dir][node];
    int deg   = g_cnt[dir][node];
    const int* adj = g_adj[dir];
    float acc[4] = {};
    for (int t = 0; t < deg; t++) {
        int u = __ldg(&adj[start + t]);
        uint2 r = __ldg((const uint2*)(g_feath + (size_t)u * D0) + lane);
        float2 f0 = __half22float2(*(const __half2*)&r.x);
        float2 f1 = __half22float2(*(const __half2*)&r.y);
        acc[0] += f0.x; acc[1] += f0.y; acc[2] += f1.x; acc[3] += f1.y;
    }
    float w = g_inv[dir][node];
    __half2* out = (__half2*)(h1 + (size_t)node * D1 + dir * D0 + lane * 4);
    out[0] = __floats2half2_rn(acc[0] * w, acc[1] * w);
    out[1] = __floats2half2_rn(acc[2] * w, acc[3] * w);
}

// ---------------- hop2: h1 fp16 (D=128) -> h2 tf32-bits [N,256] ------------
__global__ void __launch_bounds__(256) hop2_kernel(
    const __half* __restrict__ h1, float* __restrict__ h2, int n)
{
    int gid = blockIdx.x * blockDim.x + threadIdx.x;
    int node = gid >> 4;
    int lane = gid & 15;               // 16 lanes x 8 halves = 128
    int dir = blockIdx.y;
    if (node >= n) return;
    int start = g_rowptr[dir][node];
    int deg   = g_cnt[dir][node];
    const int* adj = g_adj[dir];
    float acc[8] = {};
    for (int t = 0; t < deg; t++) {
        int u = __ldg(&adj[start + t]);
        uint4 r = __ldg((const uint4*)(h1 + (size_t)u * D1) + lane);
        const __half2* h = (const __half2*)&r;
        #pragma unroll
        for (int j = 0; j < 4; j++) {
            float2 f = __half22float2(h[j]);
            acc[2 * j]     += f.x;
            acc[2 * j + 1] += f.y;
        }
    }
    float w = g_inv[dir][node];
    uint32_t o[8];
    #pragma unroll
    for (int j = 0; j < 8; j++) o[j] = f2tf(acc[j] * w);
    uint4* out = (uint4*)(h2 + (size_t)node * D2 + dir * D1 + lane * 8);
    out[0] = make_uint4(o[0], o[1], o[2], o[3]);
    out[1] = make_uint4(o[4], o[5], o[6], o[7]);
}

// ---------------- tf32 GEMM, zero in-loop conversion, reg-staged pipeline --
__device__ __forceinline__ void mma_tf32(float* c, const uint32_t* a,
                                         uint32_t b0, uint32_t b1) {
    asm volatile(
        "mma.sync.aligned.m16n8k8.row.col.f32.tf32.tf32.f32 "
        "{%0,%1,%2,%3}, {%4,%5,%6,%7}, {%8,%9}, {%0,%1,%2,%3};"
        : "+f"(c[0]), "+f"(c[1]), "+f"(c[2]), "+f"(c[3])
        : "r"(a[0]), "r"(a[1]), "r"(a[2]), "r"(a[3]), "r"(b0), "r"(b1));
}

__global__ void __launch_bounds__(256, 2) gemm_tf32_kernel(
    const float* __restrict__ A, __half* __restrict__ C, int N)
{
    __shared__ uint32_t As[128][36];   // pad 36: LDS bank = 4g+q, conflict-free
    __shared__ uint32_t Bs[32][136];   // pad 136: LDS bank = 8q+g, conflict-free
    int tid = threadIdx.x;
    int warp = tid >> 5, lane = tid & 31;
    int warpRow = warp >> 1;           // 0..3
    int warpCol = warp & 1;            // 0..1
    int g = lane >> 2, q = lane & 3;
    int blockRow = blockIdx.x * 128;
    int blockCol = blockIdx.y * 128;
    float c[2][8][4] = {};

    int am = tid >> 3;                 // A row base (0..31), +32*i
    int ak = tid & 7;                  // A float4 index in k-tile
    int bk = tid >> 5;                 // B k-row base (0..7), +8*i
    int bn = tid & 31;                 // B float4 index in n

    uint4 bufA[4], bufB[4];
    const uint4 zero4 = make_uint4(0u, 0u, 0u, 0u);

    // prologue: load k-tile 0
    #pragma unroll
    for (int i = 0; i < 4; i++) {
        int row = blockRow + am + i * 32;
        bufA[i] = (row < N) ? __ldg((const uint4*)(A + (size_t)row * D2) + ak) : zero4;
        bufB[i] = __ldg((const uint4*)(g_Wt2 + (size_t)(bk + i * 8) * D2 + blockCol) + bn);
    }

    for (int kt = 0; kt < 8; kt++) {
        #pragma unroll
        for (int i = 0; i < 4; i++) {
            *(uint4*)&As[am + i * 32][ak * 4] = bufA[i];
            *(uint4*)&Bs[bk + i * 8][bn * 4] = bufB[i];
        }
        __syncthreads();
        if (kt < 7) {
            int k0 = (kt + 1) * 32;
            #pragma unroll
            for (int i = 0; i < 4; i++) {
                int row = blockRow + am + i * 32;
                bufA[i] = (row < N) ? __ldg((const uint4*)(A + (size_t)row * D2 + k0) + ak) : zero4;
                bufB[i] = __ldg((const uint4*)(g_Wt2 + (size_t)(k0 + bk + i * 8) * D2 + blockCol) + bn);
            }
        }
        #pragma unroll
        for (int ks = 0; ks < 4; ks++) {
            int kb = ks * 8;
            uint32_t a[2][4];
            #pragma unroll
            for (int mt = 0; mt < 2; mt++) {
                int rb = warpRow * 32 + mt * 16;
                a[mt][0] = As[rb + g    ][kb + q    ];
                a[mt][1] = As[rb + g + 8][kb + q    ];
                a[mt][2] = As[rb + g    ][kb + q + 4];
                a[mt][3] = As[rb + g + 8][kb + q + 4];
            }
            #pragma unroll
            for (int nt = 0; nt < 8; nt++) {
                int cb = warpCol * 64 + nt * 8 + g;
                uint32_t b0 = Bs[kb + q    ][cb];
                uint32_t b1 = Bs[kb + q + 4][cb];
                mma_tf32(c[0][nt], a[0], b0, b1);
                mma_tf32(c[1][nt], a[1], b0, b1);
            }
        }
        __syncthreads();
    }

    #pragma unroll
    for (int mt = 0; mt < 2; mt++)
        #pragma unroll
        for (int nt = 0; nt < 8; nt++) {
            int col = blockCol + warpCol * 64 + nt * 8 + q * 2;
            int r0 = blockRow + warpRow * 32 + mt * 16 + g;
            if (r0 < N)
                *(__half2*)(C + (size_t)r0 * D2 + col) =
                    __floats2half2_rn(c[mt][nt][0], c[mt][nt][1]);
            int r1 = r0 + 8;
            if (r1 < N)
                *(__half2*)(C + (size_t)r1 * D2 + col) =
                    __floats2half2_rn(c[mt][nt][2], c[mt][nt][3]);
        }
}

// ---------------- fused hop3: aggregate P fp16, scale, bias, out fp32 ------
__global__ void __launch_bounds__(256) hop3_kernel(
    const __half* __restrict__ P, const float* __restrict__ bias,
    float* __restrict__ out, int n)
{
    int node = blockIdx.x * 8 + (threadIdx.x >> 5);
    int lane = threadIdx.x & 31;
    if (node >= n) return;
    float aI[4] = {}, aO[4] = {};
    int s0 = g_rowptr[0][node], d0 = g_cnt[0][node];
    for (int t = 0; t < d0; t++) {
        int u = __ldg(&g_adj[0][s0 + t]);
        uint2 r = __ldg((const uint2*)(P + (size_t)u * D2) + lane);
        float2 f0 = __half22float2(*(const __half2*)&r.x);
        float2 f1 = __half22float2(*(const __half2*)&r.y);
        aI[0] += f0.x; aI[1] += f0.y; aI[2] += f1.x; aI[3] += f1.y;
    }
    int s1 = g_rowptr[1][node], d1 = g_cnt[1][node];
    for (int t = 0; t < d1; t++) {
        int u = __ldg(&g_adj[1][s1 + t]);
        uint2 r = __ldg((const uint2*)(P + (size_t)u * D2 + ODIM) + lane);
        float2 f0 = __half22float2(*(const __half2*)&r.x);
        float2 f1 = __half22float2(*(const __half2*)&r.y);
        aO[0] += f0.x; aO[1] += f0.y; aO[2] += f1.x; aO[3] += f1.y;
    }
    float wi = g_inv[0][node], wo = g_inv[1][node];
    float4 b = __ldg((const float4*)bias + lane);
    float4 r;
    r.x = aI[0] * wi + aO[0] * wo + b.x;
    r.y = aI[1] * wi + aO[1] * wo + b.y;
    r.z = aI[2] * wi + aO[2] * wo + b.z;
    r.w = aI[3] * wi + aO[3] * wo + b.w;
    ((float4*)(out + (size_t)node * ODIM))[lane] = r;
}

// ---------------- launch ----------------------------------------------------
extern "C" void kernel_launch(void* const* d_in, const int* in_sizes, int n_in,
                              void* d_out, int out_size)
{
    const float* feat  = (const float*)d_in[0];
    const void*  edges = d_in[1];
    const float* W     = (const float*)d_in[2];
    const float* bias  = (const float*)d_in[3];
    float* out = (float*)d_out;

    int N = in_sizes[0] / D0;     // 50000
    int E = in_sizes[1] / 2;      // 800000

    __half *h1, *P;
    float *h2;
    cudaGetSymbolAddress((void**)&h1, g_h1h);
    cudaGetSymbolAddress((void**)&h2, g_h2);
    cudaGetSymbolAddress((void**)&P,  g_Ph);

    const int T = 256;
    int nfeat2 = N * D0 / 2;      // half2 pairs
    initA_kernel<<<(nfeat2 + T - 1) / T, T>>>(feat, N, nfeat2);
    detect_kernel<<<(E + T - 1) / T, T>>>((const unsigned*)edges, 2 * E);
    convert_count_kernel<<<(E + T - 1) / T, T>>>(edges, E);

    dim3 sgrid((N + 1023) / 1024, 2);
    scan1_kernel<<<sgrid, 1024>>>(W, N);
    scan2_kernel<<<1, 32>>>();
    scan3_kernel<<<sgrid, 1024>>>(N);
    fill_kernel<<<(E + T - 1) / T, T>>>(E);

    {
        unsigned total = (unsigned)N * 16;
        dim3 g((total + T - 1) / T, 2);
        hop1_kernel<<<g, T>>>(h1, N);
        hop2_kernel<<<g, T>>>(h1, h2, N);
    }
    {
        dim3 g((N + 127) / 128, 2);
        gemm_tf32_kernel<<<g, T>>>(h2, P, N);
    }
    hop3_kernel<<<(N + 7) / 8, T>>>(P, bias, out, N);
}

// round 8
// speedup vs baseline: 4.7275x; 1.1341x over previous
#include <cuda_runtime.h>
#include <cuda_fp16.h>
#include <cstdint>
#include <cstddef>

#define NM 50000
#define EM 800000
#define D0 64
#define D1 128
#define D2 256
#define ODIM 128
#define NB ((NM + 1023) / 1024)

// ---------------- device scratch ------------------------------------------
__device__ __half g_feath[(size_t)NM * D0];   // 6.4 MB  fp16 features
__device__ __half g_h1h[(size_t)NM * D1];     // 12.8 MB fp16
__device__ __half g_h2h[(size_t)NM * D2];     // 25.6 MB fp16 (GEMM A)
__device__ __half g_Ph[(size_t)NM * D2];      // 25.6 MB fp16 (Pin 0-127, Pout 128-255)
__device__ uint32_t g_Wt2h[(D2 / 2) * D2];    // [k2][n] half2-packed weights (B)
__device__ int    g_src[EM];
__device__ int    g_dst[EM];
__device__ int    g_adj[2][EM];
__device__ int    g_cnt[2][NM];
__device__ int    g_rowptr[2][NM];
__device__ int    g_cursor[2][NM];
__device__ float  g_inv[2][NM];
__device__ int    g_part[2][64];
__device__ int    g_flag32;

// ---------------- setup: zero counts + flag + feature->fp16 ----------------
__global__ void initA_kernel(const float* __restrict__ feat, int n, int nfeat2) {
    int i = blockIdx.x * blockDim.x + threadIdx.x;
    if (i < n) { g_cnt[0][i] = 0; g_cnt[1][i] = 0; }
    if (i == 0) g_flag32 = 0;
    if (i < nfeat2) {
        float2 f = ((const float2*)feat)[i];
        ((__half2*)g_feath)[i] = __floats2half2_rn(f.x, f.y);
    }
}

__global__ void detect_kernel(const unsigned* __restrict__ p, int n32) {
    int i = blockIdx.x * blockDim.x + threadIdx.x;
    int idx = 2 * i + 1;
    if (idx < n32 && p[idx] != 0u) g_flag32 = 1;
}

__global__ void convert_count_kernel(const void* __restrict__ e, int E) {
    int i = blockIdx.x * blockDim.x + threadIdx.x;
    if (i >= E) return;
    int s, d;
    if (g_flag32) {
        const int* p = (const int*)e;
        s = p[i]; d = p[E + i];
    } else {
        const long long* p = (const long long*)e;
        s = (int)p[i]; d = (int)p[E + i];
    }
    g_src[i] = s; g_dst[i] = d;
    atomicAdd(&g_cnt[0][d], 1);
    atomicAdd(&g_cnt[1][s], 1);
}

// scan1 also folds the weight rearrange (fp16 half2-packed along k)
// Wt2h[k2*256 + j] = {w(2k2, j), w(2k2+1, j)}
//   w(k,j) = (j<128) ? W[j][k] : W[j-128][256+k]    (W is [128,512] row-major)
__global__ void scan1_kernel(const float* __restrict__ W, int n) {
    int flat = (blockIdx.y * NB + blockIdx.x) * 1024 + threadIdx.x;
    if (flat < (D2 / 2) * D2) {
        int k2 = flat / D2, j = flat % D2;
        int base = (j < ODIM) ? j * 512 + 2 * k2 : (j - ODIM) * 512 + 256 + 2 * k2;
        float lo = W[base], hi = W[base + 1];
        __half2 h = __floats2half2_rn(lo, hi);
        g_Wt2h[flat] = *(uint32_t*)&h;
    }
    // ---- scan ----
    int dir = blockIdx.y;
    int tid = threadIdx.x;
    int i = blockIdx.x * 1024 + tid;
    int v = (i < n) ? g_cnt[dir][i] : 0;
    int lane = tid & 31, w = tid >> 5;
    int x = v;
    #pragma unroll
    for (int o = 1; o < 32; o <<= 1) {
        int y = __shfl_up_sync(0xffffffffu, x, o);
        if (lane >= o) x += y;
    }
    __shared__ int ws[32];
    if (lane == 31) ws[w] = x;
    __syncthreads();
    if (w == 0) {
        int y = ws[lane];
        #pragma unroll
        for (int o = 1; o < 32; o <<= 1) {
            int z = __shfl_up_sync(0xffffffffu, y, o);
            if (lane >= o) y += z;
        }
        ws[lane] = y;
    }
    __syncthreads();
    int excl = x - v + (w ? ws[w - 1] : 0);
    if (i < n) g_rowptr[dir][i] = excl;
    if (tid == 0) g_part[dir][blockIdx.x] = ws[31];
}

__global__ void scan2_kernel() {
    int dir = threadIdx.x;
    if (dir < 2) {
        int acc = 0;
        for (int b = 0; b < NB; b++) {
            int t = g_part[dir][b];
            g_part[dir][b] = acc;
            acc += t;
        }
    }
}

__global__ void scan3_kernel(int n) {
    int dir = blockIdx.y;
    int i = blockIdx.x * 1024 + threadIdx.x;
    if (i < n) {
        int v = g_rowptr[dir][i] + g_part[dir][blockIdx.x];
        g_rowptr[dir][i] = v;
        g_cursor[dir][i] = v;
        g_inv[dir][i] = 1.0f / fmaxf((float)g_cnt[dir][i], 1.0f);
    }
}

__global__ void fill_kernel(int E) {
    int i = blockIdx.x * blockDim.x + threadIdx.x;
    if (i >= E) return;
    int s = g_src[i], d = g_dst[i];
    int p = atomicAdd(&g_cursor[0][d], 1);
    g_adj[0][p] = s;
    int q = atomicAdd(&g_cursor[1][s], 1);
    g_adj[1][q] = d;
}

// ---------------- hop1: feat fp16 (D=64) -> h1 fp16 [N,128], MLP-4 loop ----
__global__ void __launch_bounds__(256) hop1_kernel(__half* __restrict__ h1, int n) {
    int gid = blockIdx.x * blockDim.x + threadIdx.x;
    int node = gid >> 4;
    int lane = gid & 15;               // 16 lanes x 4 halves = 64
    int dir = blockIdx.y;
    if (node >= n) return;
    int start = g_rowptr[dir][node];
    int deg   = g_cnt[dir][node];
    const int* adj = g_adj[dir] + start;
    float acc[4] = {};
    int t = 0;
    for (; t + 4 <= deg; t += 4) {
        int u0 = __ldg(&adj[t]), u1 = __ldg(&adj[t + 1]);
        int u2 = __ldg(&adj[t + 2]), u3 = __ldg(&adj[t + 3]);
        uint2 r0 = __ldg((const uint2*)(g_feath + (size_t)u0 * D0) + lane);
        uint2 r1 = __ldg((const uint2*)(g_feath + (size_t)u1 * D0) + lane);
        uint2 r2 = __ldg((const uint2*)(g_feath + (size_t)u2 * D0) + lane);
        uint2 r3 = __ldg((const uint2*)(g_feath + (size_t)u3 * D0) + lane);
        uint2 rs[4] = {r0, r1, r2, r3};
        #pragma unroll
        for (int j = 0; j < 4; j++) {
            float2 f0 = __half22float2(*(const __half2*)&rs[j].x);
            float2 f1 = __half22float2(*(const __half2*)&rs[j].y);
            acc[0] += f0.x; acc[1] += f0.y; acc[2] += f1.x; acc[3] += f1.y;
        }
    }
    for (; t < deg; t++) {
        int u = __ldg(&adj[t]);
        uint2 r = __ldg((const uint2*)(g_feath + (size_t)u * D0) + lane);
        float2 f0 = __half22float2(*(const __half2*)&r.x);
        float2 f1 = __half22float2(*(const __half2*)&r.y);
        acc[0] += f0.x; acc[1] += f0.y; acc[2] += f1.x; acc[3] += f1.y;
    }
    float w = g_inv[dir][node];
    __half2* out = (__half2*)(h1 + (size_t)node * D1 + dir * D0 + lane * 4);
    out[0] = __floats2half2_rn(acc[0] * w, acc[1] * w);
    out[1] = __floats2half2_rn(acc[2] * w, acc[3] * w);
}

// ---------------- hop2: h1 fp16 (D=128) -> h2 fp16 [N,256], MLP-4 loop -----
__global__ void __launch_bounds__(256) hop2_kernel(
    const __half* __restrict__ h1, __half* __restrict__ h2, int n)
{
    int gid = blockIdx.x * blockDim.x + threadIdx.x;
    int node = gid >> 4;
    int lane = gid & 15;               // 16 lanes x 8 halves = 128
    int dir = blockIdx.y;
    if (node >= n) return;
    int start = g_rowptr[dir][node];
    int deg   = g_cnt[dir][node];
    const int* adj = g_adj[dir] + start;
    float acc[8] = {};
    int t = 0;
    for (; t + 4 <= deg; t += 4) {
        int u0 = __ldg(&adj[t]), u1 = __ldg(&adj[t + 1]);
        int u2 = __ldg(&adj[t + 2]), u3 = __ldg(&adj[t + 3]);
        uint4 r0 = __ldg((const uint4*)(h1 + (size_t)u0 * D1) + lane);
        uint4 r1 = __ldg((const uint4*)(h1 + (size_t)u1 * D1) + lane);
        uint4 r2 = __ldg((const uint4*)(h1 + (size_t)u2 * D1) + lane);
        uint4 r3 = __ldg((const uint4*)(h1 + (size_t)u3 * D1) + lane);
        uint4 rs[4] = {r0, r1, r2, r3};
        #pragma unroll
        for (int m = 0; m < 4; m++) {
            const __half2* h = (const __half2*)&rs[m];
            #pragma unroll
            for (int j = 0; j < 4; j++) {
                float2 f = __half22float2(h[j]);
                acc[2 * j]     += f.x;
                acc[2 * j + 1] += f.y;
            }
        }
    }
    for (; t < deg; t++) {
        int u = __ldg(&adj[t]);
        uint4 r = __ldg((const uint4*)(h1 + (size_t)u * D1) + lane);
        const __half2* h = (const __half2*)&r;
        #pragma unroll
        for (int j = 0; j < 4; j++) {
            float2 f = __half22float2(h[j]);
            acc[2 * j]     += f.x;
            acc[2 * j + 1] += f.y;
        }
    }
    float w = g_inv[dir][node];
    __half2 o[4];
    #pragma unroll
    for (int j = 0; j < 4; j++)
        o[j] = __floats2half2_rn(acc[2 * j] * w, acc[2 * j + 1] * w);
    *(uint4*)(h2 + (size_t)node * D2 + dir * D1 + lane * 8) = *(uint4*)o;
}

// ---------------- fp16 tensor-core GEMM: P = h2 @ Wt2, fp16 out ------------
__device__ __forceinline__ void mma_f16(float* c, const uint32_t* a,
                                        uint32_t b0, uint32_t b1) {
    asm volatile(
        "mma.sync.aligned.m16n8k16.row.col.f32.f16.f16.f32 "
        "{%0,%1,%2,%3}, {%4,%5,%6,%7}, {%8,%9}, {%0,%1,%2,%3};"
        : "+f"(c[0]), "+f"(c[1]), "+f"(c[2]), "+f"(c[3])
        : "r"(a[0]), "r"(a[1]), "r"(a[2]), "r"(a[3]), "r"(b0), "r"(b1));
}

__global__ void __launch_bounds__(256, 2) gemm_f16_kernel(
    const __half* __restrict__ A, __half* __restrict__ C, int N)
{
    // half2-packed along k: As[row][k2], Bs[k2][n]
    __shared__ uint32_t As[128][20];   // pad 20: bank = 20g+q mod 32, injective
    __shared__ uint32_t Bs[16][136];   // pad 136: bank = 8q+g, injective
    int tid = threadIdx.x;
    int warp = tid >> 5, lane = tid & 31;
    int warpRow = warp >> 1;           // 0..3 (32 rows)
    int warpCol = warp & 1;            // 0..1 (64 cols)
    int g = lane >> 2, q = lane & 3;
    int blockRow = blockIdx.x * 128;
    int blockCol = blockIdx.y * 128;
    float c[2][8][4] = {};

    // global load mapping (2 uint4 each for A and B per tile)
    int arow = tid >> 2;               // 0..63 (+64)
    int ac4  = tid & 3;                // uint4 within row k-tile (16 u32)
    int bk2  = tid >> 5;               // 0..7 (+8)
    int bn4  = tid & 31;               // uint4 within 128-col tile

    const uint4* Ag = (const uint4*)A;       // row stride 32 uint4
    const uint4* Bg = (const uint4*)g_Wt2h;  // k2 stride 64 uint4
    uint4 bufA[2], bufB[2];
    const uint4 zero4 = make_uint4(0u, 0u, 0u, 0u);

    // prologue: k-tile 0
    #pragma unroll
    for (int i = 0; i < 2; i++) {
        int row = blockRow + arow + i * 64;
        bufA[i] = (row < N) ? __ldg(Ag + (size_t)row * 32 + ac4) : zero4;
        bufB[i] = __ldg(Bg + (size_t)(bk2 + i * 8) * 64 + (blockCol >> 2) + bn4);
    }

    for (int kt = 0; kt < 8; kt++) {
        #pragma unroll
        for (int i = 0; i < 2; i++) {
            *(uint4*)&As[arow + i * 64][ac4 * 4] = bufA[i];
            *(uint4*)&Bs[bk2 + i * 8][bn4 * 4] = bufB[i];
        }
        __syncthreads();
        if (kt < 7) {
            #pragma unroll
            for (int i = 0; i < 2; i++) {
                int row = blockRow + arow + i * 64;
                bufA[i] = (row < N) ? __ldg(Ag + (size_t)row * 32 + (kt + 1) * 4 + ac4) : zero4;
                bufB[i] = __ldg(Bg + (size_t)((kt + 1) * 16 + bk2 + i * 8) * 64 + (blockCol >> 2) + bn4);
            }
        }
        #pragma unroll
        for (int ks = 0; ks < 2; ks++) {
            int kb = ks * 8;               // half2 units
            uint32_t a[2][4];
            #pragma unroll
            for (int mt = 0; mt < 2; mt++) {
                int rb = warpRow * 32 + mt * 16;
                a[mt][0] = As[rb + g    ][kb + q    ];
                a[mt][1] = As[rb + g + 8][kb + q    ];
                a[mt][2] = As[rb + g    ][kb + q + 4];
                a[mt][3] = As[rb + g + 8][kb + q + 4];
            }
            #pragma unroll
            for (int nt = 0; nt < 8; nt++) {
                int cb = warpCol * 64 + nt * 8 + g;
                uint32_t b0 = Bs[kb + q    ][cb];
                uint32_t b1 = Bs[kb + q + 4][cb];
                mma_f16(c[0][nt], a[0], b0, b1);
                mma_f16(c[1][nt], a[1], b0, b1);
            }
        }
        __syncthreads();
    }

    #pragma unroll
    for (int mt = 0; mt < 2; mt++)
        #pragma unroll
        for (int nt = 0; nt < 8; nt++) {
            int col = blockCol + warpCol * 64 + nt * 8 + q * 2;
            int r0 = blockRow + warpRow * 32 + mt * 16 + g;
            if (r0 < N)
                *(__half2*)(C + (size_t)r0 * D2 + col) =
                    __floats2half2_rn(c[mt][nt][0], c[mt][nt][1]);
            int r1 = r0 + 8;
            if (r1 < N)
                *(__half2*)(C + (size_t)r1 * D2 + col) =
                    __floats2half2_rn(c[mt][nt][2], c[mt][nt][3]);
        }
}

// ---------------- fused hop3: aggregate P fp16, scale, bias, MLP-4 ---------
__global__ void __launch_bounds__(256) hop3_kernel(
    const __half* __restrict__ P, const float* __restrict__ bias,
    float* __restrict__ out, int n)
{
    int node = blockIdx.x * 8 + (threadIdx.x >> 5);
    int lane = threadIdx.x & 31;
    if (node >= n) return;
    float aI[4] = {}, aO[4] = {};
    #pragma unroll
    for (int dir = 0; dir < 2; dir++) {
        float* acc = dir ? aO : aI;
        int off = dir ? ODIM : 0;
        int start = g_rowptr[dir][node];
        int deg   = g_cnt[dir][node];
        const int* adj = g_adj[dir] + start;
        int t = 0;
        for (; t + 4 <= deg; t += 4) {
            int u0 = __ldg(&adj[t]), u1 = __ldg(&adj[t + 1]);
            int u2 = __ldg(&adj[t + 2]), u3 = __ldg(&adj[t + 3]);
            uint2 r0 = __ldg((const uint2*)(P + (size_t)u0 * D2 + off) + lane);
            uint2 r1 = __ldg((const uint2*)(P + (size_t)u1 * D2 + off) + lane);
            uint2 r2 = __ldg((const uint2*)(P + (size_t)u2 * D2 + off) + lane);
            uint2 r3 = __ldg((const uint2*)(P + (size_t)u3 * D2 + off) + lane);
            uint2 rs[4] = {r0, r1, r2, r3};
            #pragma unroll
            for (int j = 0; j < 4; j++) {
                float2 f0 = __half22float2(*(const __half2*)&rs[j].x);
                float2 f1 = __half22float2(*(const __half2*)&rs[j].y);
                acc[0] += f0.x; acc[1] += f0.y; acc[2] += f1.x; acc[3] += f1.y;
            }
        }
        for (; t < deg; t++) {
            int u = __ldg(&adj[t]);
            uint2 r = __ldg((const uint2*)(P + (size_t)u * D2 + off) + lane);
            float2 f0 = __half22float2(*(const __half2*)&r.x);
            float2 f1 = __half22float2(*(const __half2*)&r.y);
            acc[0] += f0.x; acc[1] += f0.y; acc[2] += f1.x; acc[3] += f1.y;
        }
    }
    float wi = g_inv[0][node], wo = g_inv[1][node];
    float4 b = __ldg((const float4*)bias + lane);
    float4 r;
    r.x = aI[0] * wi + aO[0] * wo + b.x;
    r.y = aI[1] * wi + aO[1] * wo + b.y;
    r.z = aI[2] * wi + aO[2] * wo + b.z;
    r.w = aI[3] * wi + aO[3] * wo + b.w;
    ((float4*)(out + (size_t)node * ODIM))[lane] = r;
}

// ---------------- launch ----------------------------------------------------
extern "C" void kernel_launch(void* const* d_in, const int* in_sizes, int n_in,
                              void* d_out, int out_size)
{
    const float* feat  = (const float*)d_in[0];
    const void*  edges = d_in[1];
    const float* W     = (const float*)d_in[2];
    const float* bias  = (const float*)d_in[3];
    float* out = (float*)d_out;

    int N = in_sizes[0] / D0;     // 50000
    int E = in_sizes[1] / 2;      // 800000

    __half *h1, *h2, *P;
    cudaGetSymbolAddress((void**)&h1, g_h1h);
    cudaGetSymbolAddress((void**)&h2, g_h2h);
    cudaGetSymbolAddress((void**)&P,  g_Ph);

    const int T = 256;
    int nfeat2 = N * D0 / 2;
    initA_kernel<<<(nfeat2 + T - 1) / T, T>>>(feat, N, nfeat2);
    detect_kernel<<<(E + T - 1) / T, T>>>((const unsigned*)edges, 2 * E);
    convert_count_kernel<<<(E + T - 1) / T, T>>>(edges, E);

    dim3 sgrid((N + 1023) / 1024, 2);
    scan1_kernel<<<sgrid, 1024>>>(W, N);
    scan2_kernel<<<1, 32>>>();
    scan3_kernel<<<sgrid, 1024>>>(N);
    fill_kernel<<<(E + T - 1) / T, T>>>(E);

    {
        unsigned total = (unsigned)N * 16;
        dim3 g((total + T - 1) / T, 2);
        hop1_kernel<<<g, T>>>(h1, N);
        hop2_kernel<<<g, T>>>(h1, h2, N);
    }
    {
        dim3 g((N + 127) / 128, 2);
        gemm_f16_kernel<<<g, T>>>(h2, P, N);
    }
    hop3_kernel<<<(N + 7) / 8, T>>>(P, bias, out, N);
}

// round 9
// speedup vs baseline: 4.8231x; 1.0202x over previous
#include <cuda_runtime.h>
#include <cuda_fp16.h>
#include <cstdint>
#include <cstddef>

#define NM 50000
#define EM 800000
#define D0 64
#define D1 128
#define D2 256
#define ODIM 128
#define NB ((NM + 1023) / 1024)

// ---------------- device scratch ------------------------------------------
__device__ __half g_feath[(size_t)NM * D0];   // 6.4 MB  fp16 features
__device__ __half g_h1h[(size_t)NM * D1];     // 12.8 MB fp16
__device__ __half g_h2h[(size_t)NM * D2];     // 25.6 MB fp16 (GEMM A)
__device__ __half g_Ph[(size_t)NM * D2];      // 25.6 MB fp16 (Pin 0-127, Pout 128-255)
__device__ uint32_t g_Wt2h[(D2 / 2) * D2];    // [k2][n] half2-packed weights (B)
__device__ int    g_src[EM];
__device__ int    g_dst[EM];
__device__ int    g_adj[2][EM];
__device__ int    g_cnt[2][NM];
__device__ int    g_rowptr[2][NM];
__device__ int    g_cursor[2][NM];
__device__ float  g_inv[2][NM];
__device__ int    g_part[2][64];
__device__ int    g_flag32;                   // static-init 0; reset by scan1 each pass

// ------ setup: zero counts + feature->fp16 + int32/int64 detection --------
__global__ void initA_kernel(const float* __restrict__ feat,
                             const unsigned* __restrict__ edges32,
                             int n, int nfeat2, int E) {
    int i = blockIdx.x * blockDim.x + threadIdx.x;
    if (i < n) { g_cnt[0][i] = 0; g_cnt[1][i] = 0; }
    if (i < nfeat2) {
        float2 f = ((const float2*)feat)[i];
        ((__half2*)g_feath)[i] = __floats2half2_rn(f.x, f.y);
    }
    // detection: if edges are int64 (values < 50000) every odd word is 0.
    unsigned hiw = (i < E) ? edges32[2 * i + 1] : 0u;
    if (__any_sync(__activemask(), hiw != 0u) && (threadIdx.x & 31) == 0 && hiw != 0u)
        g_flag32 = 1;   // benign race: all writers store 1
}

__global__ void convert_count_kernel(const void* __restrict__ e, int E) {
    int i = blockIdx.x * blockDim.x + threadIdx.x;
    if (i >= E) return;
    int s, d;
    if (g_flag32) {
        const int* p = (const int*)e;
        s = p[i]; d = p[E + i];
    } else {
        const long long* p = (const long long*)e;
        s = (int)p[i]; d = (int)p[E + i];
    }
    g_src[i] = s; g_dst[i] = d;
    atomicAdd(&g_cnt[0][d], 1);
    atomicAdd(&g_cnt[1][s], 1);
}

// scan1: per-block exclusive scan + raw block totals; folds W rearrange and
// the g_flag32 reset (runs after convert_count consumed the flag).
__global__ void scan1_kernel(const float* __restrict__ W, int n) {
    int flat = (blockIdx.y * NB + blockIdx.x) * 1024 + threadIdx.x;
    if (flat < (D2 / 2) * D2) {
        int k2 = flat / D2, j = flat % D2;
        int base = (j < ODIM) ? j * 512 + 2 * k2 : (j - ODIM) * 512 + 256 + 2 * k2;
        __half2 h = __floats2half2_rn(W[base], W[base + 1]);
        g_Wt2h[flat] = *(uint32_t*)&h;
    }
    if (flat == 0) g_flag32 = 0;      // reset for next replay
    int dir = blockIdx.y;
    int tid = threadIdx.x;
    int i = blockIdx.x * 1024 + tid;
    int v = (i < n) ? g_cnt[dir][i] : 0;
    int lane = tid & 31, w = tid >> 5;
    int x = v;
    #pragma unroll
    for (int o = 1; o < 32; o <<= 1) {
        int y = __shfl_up_sync(0xffffffffu, x, o);
        if (lane >= o) x += y;
    }
    __shared__ int ws[32];
    if (lane == 31) ws[w] = x;
    __syncthreads();
    if (w == 0) {
        int y = ws[lane];
        #pragma unroll
        for (int o = 1; o < 32; o <<= 1) {
            int z = __shfl_up_sync(0xffffffffu, y, o);
            if (lane >= o) y += z;
        }
        ws[lane] = y;
    }
    __syncthreads();
    int excl = x - v + (w ? ws[w - 1] : 0);
    if (i < n) g_rowptr[dir][i] = excl;
    if (tid == 0) g_part[dir][blockIdx.x] = ws[31];   // raw block total
}

// scan3: adds prefix of block totals (computed in-block) and finalizes CSR.
__global__ void scan3_kernel(int n) {
    int dir = blockIdx.y;
    __shared__ int base_s;
    if (threadIdx.x < 32) {
        int v = 0;
        for (int b = (int)threadIdx.x; b < (int)blockIdx.x; b += 32)
            v += g_part[dir][b];
        #pragma unroll
        for (int o = 16; o; o >>= 1) v += __shfl_down_sync(0xffffffffu, v, o);
        if (threadIdx.x == 0) base_s = v;
    }
    __syncthreads();
    int i = blockIdx.x * 1024 + threadIdx.x;
    if (i < n) {
        int v = g_rowptr[dir][i] + base_s;
        g_rowptr[dir][i] = v;
        g_cursor[dir][i] = v;
        g_inv[dir][i] = 1.0f / fmaxf((float)g_cnt[dir][i], 1.0f);
    }
}

__global__ void fill_kernel(int E) {
    int i = blockIdx.x * blockDim.x + threadIdx.x;
    if (i >= E) return;
    int s = g_src[i], d = g_dst[i];
    int p = atomicAdd(&g_cursor[0][d], 1);
    g_adj[0][p] = s;
    int q = atomicAdd(&g_cursor[1][s], 1);
    g_adj[1][q] = d;
}

// ---------------- hop1: feat fp16 (D=64) -> h1 fp16 [N,128], MLP-8 --------
__global__ void __launch_bounds__(256) hop1_kernel(__half* __restrict__ h1, int n) {
    int gid = blockIdx.x * blockDim.x + threadIdx.x;
    int node = gid >> 4;
    int lane = gid & 15;               // 16 lanes x 4 halves = 64
    int dir = blockIdx.y;
    if (node >= n) return;
    int start = g_rowptr[dir][node];
    int deg   = g_cnt[dir][node];
    const int* adj = g_adj[dir] + start;
    float acc[4] = {};
    int t = 0;
    for (; t + 8 <= deg; t += 8) {
        int u[8];
        #pragma unroll
        for (int j = 0; j < 8; j++) u[j] = __ldg(&adj[t + j]);
        uint2 rs[8];
        #pragma unroll
        for (int j = 0; j < 8; j++)
            rs[j] = __ldg((const uint2*)(g_feath + (size_t)u[j] * D0) + lane);
        #pragma unroll
        for (int j = 0; j < 8; j++) {
            float2 f0 = __half22float2(*(const __half2*)&rs[j].x);
            float2 f1 = __half22float2(*(const __half2*)&rs[j].y);
            acc[0] += f0.x; acc[1] += f0.y; acc[2] += f1.x; acc[3] += f1.y;
        }
    }
    for (; t < deg; t++) {
        int u = __ldg(&adj[t]);
        uint2 r = __ldg((const uint2*)(g_feath + (size_t)u * D0) + lane);
        float2 f0 = __half22float2(*(const __half2*)&r.x);
        float2 f1 = __half22float2(*(const __half2*)&r.y);
        acc[0] += f0.x; acc[1] += f0.y; acc[2] += f1.x; acc[3] += f1.y;
    }
    float w = g_inv[dir][node];
    __half2* out = (__half2*)(h1 + (size_t)node * D1 + dir * D0 + lane * 4);
    out[0] = __floats2half2_rn(acc[0] * w, acc[1] * w);
    out[1] = __floats2half2_rn(acc[2] * w, acc[3] * w);
}

// ---------------- hop2: h1 fp16 (D=128) -> h2 fp16 [N,256], MLP-8 ---------
__global__ void __launch_bounds__(256) hop2_kernel(
    const __half* __restrict__ h1, __half* __restrict__ h2, int n)
{
    int gid = blockIdx.x * blockDim.x + threadIdx.x;
    int node = gid >> 4;
    int lane = gid & 15;               // 16 lanes x 8 halves = 128
    int dir = blockIdx.y;
    if (node >= n) return;
    int start = g_rowptr[dir][node];
    int deg   = g_cnt[dir][node];
    const int* adj = g_adj[dir] + start;
    float acc[8] = {};
    int t = 0;
    for (; t + 8 <= deg; t += 8) {
        int u[8];
        #pragma unroll
        for (int j = 0; j < 8; j++) u[j] = __ldg(&adj[t + j]);
        uint4 rs[8];
        #pragma unroll
        for (int j = 0; j < 8; j++)
            rs[j] = __ldg((const uint4*)(h1 + (size_t)u[j] * D1) + lane);
        #pragma unroll
        for (int m = 0; m < 8; m++) {
            const __half2* h = (const __half2*)&rs[m];
            #pragma unroll
            for (int j = 0; j < 4; j++) {
                float2 f = __half22float2(h[j]);
                acc[2 * j]     += f.x;
                acc[2 * j + 1] += f.y;
            }
        }
    }
    for (; t < deg; t++) {
        int u = __ldg(&adj[t]);
        uint4 r = __ldg((const uint4*)(h1 + (size_t)u * D1) + lane);
        const __half2* h = (const __half2*)&r;
        #pragma unroll
        for (int j = 0; j < 4; j++) {
            float2 f = __half22float2(h[j]);
            acc[2 * j]     += f.x;
            acc[2 * j + 1] += f.y;
        }
    }
    float w = g_inv[dir][node];
    __half2 o[4];
    #pragma unroll
    for (int j = 0; j < 4; j++)
        o[j] = __floats2half2_rn(acc[2 * j] * w, acc[2 * j + 1] * w);
    *(uint4*)(h2 + (size_t)node * D2 + dir * D1 + lane * 8) = *(uint4*)o;
}

// ---------------- fp16 tensor-core GEMM: P = h2 @ Wt2, fp16 out ------------
__device__ __forceinline__ void mma_f16(float* c, const uint32_t* a,
                                        uint32_t b0, uint32_t b1) {
    asm volatile(
        "mma.sync.aligned.m16n8k16.row.col.f32.f16.f16.f32 "
        "{%0,%1,%2,%3}, {%4,%5,%6,%7}, {%8,%9}, {%0,%1,%2,%3};"
        : "+f"(c[0]), "+f"(c[1]), "+f"(c[2]), "+f"(c[3])
        : "r"(a[0]), "r"(a[1]), "r"(a[2]), "r"(a[3]), "r"(b0), "r"(b1));
}

__global__ void __launch_bounds__(256, 2) gemm_f16_kernel(
    const __half* __restrict__ A, __half* __restrict__ C, int N)
{
    __shared__ uint32_t As[128][20];   // pad 20: conflict-free fragment LDS
    __shared__ uint32_t Bs[16][136];   // pad 136: conflict-free
    int tid = threadIdx.x;
    int warp = tid >> 5, lane = tid & 31;
    int warpRow = warp >> 1;
    int warpCol = warp & 1;
    int g = lane >> 2, q = lane & 3;
    int blockRow = blockIdx.x * 128;
    int blockCol = blockIdx.y * 128;
    float c[2][8][4] = {};

    int arow = tid >> 2;
    int ac4  = tid & 3;
    int bk2  = tid >> 5;
    int bn4  = tid & 31;

    const uint4* Ag = (const uint4*)A;
    const uint4* Bg = (const uint4*)g_Wt2h;
    uint4 bufA[2], bufB[2];
    const uint4 zero4 = make_uint4(0u, 0u, 0u, 0u);

    #pragma unroll
    for (int i = 0; i < 2; i++) {
        int row = blockRow + arow + i * 64;
        bufA[i] = (row < N) ? __ldg(Ag + (size_t)row * 32 + ac4) : zero4;
        bufB[i] = __ldg(Bg + (size_t)(bk2 + i * 8) * 64 + (blockCol >> 2) + bn4);
    }

    for (int kt = 0; kt < 8; kt++) {
        #pragma unroll
        for (int i = 0; i < 2; i++) {
            *(uint4*)&As[arow + i * 64][ac4 * 4] = bufA[i];
            *(uint4*)&Bs[bk2 + i * 8][bn4 * 4] = bufB[i];
        }
        __syncthreads();
        if (kt < 7) {
            #pragma unroll
            for (int i = 0; i < 2; i++) {
                int row = blockRow + arow + i * 64;
                bufA[i] = (row < N) ? __ldg(Ag + (size_t)row * 32 + (kt + 1) * 4 + ac4) : zero4;
                bufB[i] = __ldg(Bg + (size_t)((kt + 1) * 16 + bk2 + i * 8) * 64 + (blockCol >> 2) + bn4);
            }
        }
        #pragma unroll
        for (int ks = 0; ks < 2; ks++) {
            int kb = ks * 8;
            uint32_t a[2][4];
            #pragma unroll
            for (int mt = 0; mt < 2; mt++) {
                int rb = warpRow * 32 + mt * 16;
                a[mt][0] = As[rb + g    ][kb + q    ];
                a[mt][1] = As[rb + g + 8][kb + q    ];
                a[mt][2] = As[rb + g    ][kb + q + 4];
                a[mt][3] = As[rb + g + 8][kb + q + 4];
            }
            #pragma unroll
            for (int nt = 0; nt < 8; nt++) {
                int cb = warpCol * 64 + nt * 8 + g;
                uint32_t b0 = Bs[kb + q    ][cb];
                uint32_t b1 = Bs[kb + q + 4][cb];
                mma_f16(c[0][nt], a[0], b0, b1);
                mma_f16(c[1][nt], a[1], b0, b1);
            }
        }
        __syncthreads();
    }

    #pragma unroll
    for (int mt = 0; mt < 2; mt++)
        #pragma unroll
        for (int nt = 0; nt < 8; nt++) {
            int col = blockCol + warpCol * 64 + nt * 8 + q * 2;
            int r0 = blockRow + warpRow * 32 + mt * 16 + g;
            if (r0 < N)
                *(__half2*)(C + (size_t)r0 * D2 + col) =
                    __floats2half2_rn(c[mt][nt][0], c[mt][nt][1]);
            int r1 = r0 + 8;
            if (r1 < N)
                *(__half2*)(C + (size_t)r1 * D2 + col) =
                    __floats2half2_rn(c[mt][nt][2], c[mt][nt][3]);
        }
}

// ---------------- fused hop3: aggregate P fp16, scale, bias, MLP-8 --------
__global__ void __launch_bounds__(256) hop3_kernel(
    const __half* __restrict__ P, const float* __restrict__ bias,
    float* __restrict__ out, int n)
{
    int node = blockIdx.x * 8 + (threadIdx.x >> 5);
    int lane = threadIdx.x & 31;
    if (node >= n) return;
    float aI[4] = {}, aO[4] = {};
    #pragma unroll
    for (int dir = 0; dir < 2; dir++) {
        float* acc = dir ? aO : aI;
        int off = dir ? ODIM : 0;
        int start = g_rowptr[dir][node];
        int deg   = g_cnt[dir][node];
        const int* adj = g_adj[dir] + start;
        int t = 0;
        for (; t + 8 <= deg; t += 8) {
            int u[8];
            #pragma unroll
            for (int j = 0; j < 8; j++) u[j] = __ldg(&adj[t + j]);
            uint2 rs[8];
            #pragma unroll
            for (int j = 0; j < 8; j++)
                rs[j] = __ldg((const uint2*)(P + (size_t)u[j] * D2 + off) + lane);
            #pragma unroll
            for (int j = 0; j < 8; j++) {
                float2 f0 = __half22float2(*(const __half2*)&rs[j].x);
                float2 f1 = __half22float2(*(const __half2*)&rs[j].y);
                acc[0] += f0.x; acc[1] += f0.y; acc[2] += f1.x; acc[3] += f1.y;
            }
        }
        for (; t < deg; t++) {
            int u = __ldg(&adj[t]);
            uint2 r = __ldg((const uint2*)(P + (size_t)u * D2 + off) + lane);
            float2 f0 = __half22float2(*(const __half2*)&r.x);
            float2 f1 = __half22float2(*(const __half2*)&r.y);
            acc[0] += f0.x; acc[1] += f0.y; acc[2] += f1.x; acc[3] += f1.y;
        }
    }
    float wi = g_inv[0][node], wo = g_inv[1][node];
    float4 b = __ldg((const float4*)bias + lane);
    float4 r;
    r.x = aI[0] * wi + aO[0] * wo + b.x;
    r.y = aI[1] * wi + aO[1] * wo + b.y;
    r.z = aI[2] * wi + aO[2] * wo + b.z;
    r.w = aI[3] * wi + aO[3] * wo + b.w;
    ((float4*)(out + (size_t)node * ODIM))[lane] = r;
}

// ---------------- launch ----------------------------------------------------
extern "C" void kernel_launch(void* const* d_in, const int* in_sizes, int n_in,
                              void* d_out, int out_size)
{
    const float* feat  = (const float*)d_in[0];
    const void*  edges = d_in[1];
    const float* W     = (const float*)d_in[2];
    const float* bias  = (const float*)d_in[3];
    float* out = (float*)d_out;

    int N = in_sizes[0] / D0;     // 50000
    int E = in_sizes[1] / 2;      // 800000

    __half *h1, *h2, *P;
    cudaGetSymbolAddress((void**)&h1, g_h1h);
    cudaGetSymbolAddress((void**)&h2, g_h2h);
    cudaGetSymbolAddress((void**)&P,  g_Ph);

    const int T = 256;
    int nfeat2 = N * D0 / 2;
    initA_kernel<<<(nfeat2 + T - 1) / T, T>>>(feat, (const unsigned*)edges, N, nfeat2, E);
    convert_count_kernel<<<(E + T - 1) / T, T>>>(edges, E);

    dim3 sgrid((N + 1023) / 1024, 2);
    scan1_kernel<<<sgrid, 1024>>>(W, N);
    scan3_kernel<<<sgrid, 1024>>>(N);
    fill_kernel<<<(E + T - 1) / T, T>>>(E);

    {
        unsigned total = (unsigned)N * 16;
        dim3 g((total + T - 1) / T, 2);
        hop1_kernel<<<g, T>>>(h1, N);
        hop2_kernel<<<g, T>>>(h1, h2, N);
    }
    {
        dim3 g((N + 127) / 128, 2);
        gemm_f16_kernel<<<g, T>>>(h2, P, N);
    }
    hop3_kernel<<<(N + 7) / 8, T>>>(P, bias, out, N);
}

// round 10
// speedup vs baseline: 4.8338x; 1.0022x over previous
#include <cuda_runtime.h>
#include <cuda_fp16.h>
#include <cstdint>
#include <cstddef>

#define NM 50000
#define EM 800000
#define D0 64
#define D1 128
#define D2 256
#define ODIM 128
#define NB ((NM + 1023) / 1024)

// ---------------- device scratch ------------------------------------------
__device__ __half g_feath[(size_t)NM * D0];   // 6.4 MB  fp16 features
__device__ __half g_h1h[(size_t)NM * D1];     // 12.8 MB fp16
__device__ __half g_h2h[(size_t)NM * D2];     // 25.6 MB fp16 (GEMM A)
__device__ __half g_Ph[(size_t)NM * D2];      // 25.6 MB fp16 (Pin 0-127, Pout 128-255)
__device__ uint32_t g_Wt2h[(D2 / 2) * D2];    // [k2][n] half2-packed weights (B)
__device__ int    g_src[EM];
__device__ int    g_dst[EM];
__device__ int    g_adj[2][EM];
__device__ int    g_cnt[2][NM];
__device__ int    g_rowptr[2][NM];
__device__ int    g_cursor[2][NM];
__device__ float  g_inv[2][NM];
__device__ int    g_part[2][64];
__device__ int    g_ready[2][64];             // publish flags for fused scan
__device__ int    g_flag32;                   // static-init 0; reset by scan each pass

// ------ setup: zero counts + feature->fp16 + int32/int64 detection --------
__global__ void initA_kernel(const float* __restrict__ feat,
                             const unsigned* __restrict__ edges32,
                             int n, int nfeat2, int E) {
    int i = blockIdx.x * blockDim.x + threadIdx.x;
    if (i < n) { g_cnt[0][i] = 0; g_cnt[1][i] = 0; }
    if (i < nfeat2) {
        float2 f = ((const float2*)feat)[i];
        ((__half2*)g_feath)[i] = __floats2half2_rn(f.x, f.y);
    }
    // detection: if edges are int64 (values < 50000) every odd word is 0.
    unsigned hiw = (i < E) ? edges32[2 * i + 1] : 0u;
    if (__any_sync(__activemask(), hiw != 0u) && (threadIdx.x & 31) == 0 && hiw != 0u)
        g_flag32 = 1;   // benign race: all writers store 1
}

// convert + count; also resets scan publish flags for this replay
__global__ void convert_count_kernel(const void* __restrict__ e, int E) {
    int i = blockIdx.x * blockDim.x + threadIdx.x;
    if (i < 128) ((int*)g_ready)[i] = 0;
    if (i >= E) return;
    int s, d;
    if (g_flag32) {
        const int* p = (const int*)e;
        s = p[i]; d = p[E + i];
    } else {
        const long long* p = (const long long*)e;
        s = (int)p[i]; d = (int)p[E + i];
    }
    g_src[i] = s; g_dst[i] = d;
    atomicAdd(&g_cnt[0][d], 1);
    atomicAdd(&g_cnt[1][s], 1);
}

// ---- fused single-pass scan: block scan + cross-block spin-prefix --------
// Also folds W rearrange and g_flag32 reset. Grid (NB, 2) = 98 blocks of
// 1024 <= 148 SMs -> all co-resident in wave 1, so spinning is deadlock-free.
__global__ void scan_fused_kernel(const float* __restrict__ W, int n) {
    int flat = (blockIdx.y * NB + blockIdx.x) * 1024 + threadIdx.x;
    if (flat < (D2 / 2) * D2) {
        int k2 = flat / D2, j = flat % D2;
        int base = (j < ODIM) ? j * 512 + 2 * k2 : (j - ODIM) * 512 + 256 + 2 * k2;
        __half2 h = __floats2half2_rn(W[base], W[base + 1]);
        g_Wt2h[flat] = *(uint32_t*)&h;
    }
    if (flat == 0) g_flag32 = 0;      // reset for next replay

    int dir = blockIdx.y;
    int tid = threadIdx.x;
    int i = blockIdx.x * 1024 + tid;
    int v = (i < n) ? g_cnt[dir][i] : 0;
    int lane = tid & 31, w = tid >> 5;
    int x = v;
    #pragma unroll
    for (int o = 1; o < 32; o <<= 1) {
        int y = __shfl_up_sync(0xffffffffu, x, o);
        if (lane >= o) x += y;
    }
    __shared__ int ws[32];
    __shared__ int base_s;
    if (lane == 31) ws[w] = x;
    __syncthreads();
    if (w == 0) {
        int y = ws[lane];
        #pragma unroll
        for (int o = 1; o < 32; o <<= 1) {
            int z = __shfl_up_sync(0xffffffffu, y, o);
            if (lane >= o) y += z;
        }
        ws[lane] = y;
    }
    __syncthreads();
    int excl = x - v + (w ? ws[w - 1] : 0);

    // publish this block's total, then sum all predecessors (spin until ready)
    if (tid == 0) {
        g_part[dir][blockIdx.x] = ws[31];
        __threadfence();
        atomicExch(&g_ready[dir][blockIdx.x], 1);
    }
    if (w == 0) {
        int acc = 0;
        for (int b = lane; b < (int)blockIdx.x; b += 32) {
            while (atomicAdd(&g_ready[dir][b], 0) == 0) { }
            acc += g_part[dir][b];
        }
        #pragma unroll
        for (int o = 16; o; o >>= 1) acc += __shfl_down_sync(0xffffffffu, acc, o);
        if (lane == 0) base_s = acc;
    }
    __syncthreads();
    if (i < n) {
        int r = excl + base_s;
        g_rowptr[dir][i] = r;
        g_cursor[dir][i] = r;
        g_inv[dir][i] = 1.0f / fmaxf((float)v, 1.0f);
    }
}

__global__ void fill_kernel(int E) {
    int i = blockIdx.x * blockDim.x + threadIdx.x;
    if (i >= E) return;
    int s = g_src[i], d = g_dst[i];
    int p = atomicAdd(&g_cursor[0][d], 1);
    g_adj[0][p] = s;
    int q = atomicAdd(&g_cursor[1][s], 1);
    g_adj[1][q] = d;
}

// ---------------- hop1: feat fp16 (D=64) -> h1 fp16 [N,128], MLP-8 --------
__global__ void __launch_bounds__(256) hop1_kernel(__half* __restrict__ h1, int n) {
    int gid = blockIdx.x * blockDim.x + threadIdx.x;
    int node = gid >> 4;
    int lane = gid & 15;
    int dir = blockIdx.y;
    if (node >= n) return;
    int start = g_rowptr[dir][node];
    int deg   = g_cnt[dir][node];
    const int* adj = g_adj[dir] + start;
    float acc[4] = {};
    int t = 0;
    for (; t + 8 <= deg; t += 8) {
        int u[8];
        #pragma unroll
        for (int j = 0; j < 8; j++) u[j] = __ldg(&adj[t + j]);
        uint2 rs[8];
        #pragma unroll
        for (int j = 0; j < 8; j++)
            rs[j] = __ldg((const uint2*)(g_feath + (size_t)u[j] * D0) + lane);
        #pragma unroll
        for (int j = 0; j < 8; j++) {
            float2 f0 = __half22float2(*(const __half2*)&rs[j].x);
            float2 f1 = __half22float2(*(const __half2*)&rs[j].y);
            acc[0] += f0.x; acc[1] += f0.y; acc[2] += f1.x; acc[3] += f1.y;
        }
    }
    for (; t < deg; t++) {
        int u = __ldg(&adj[t]);
        uint2 r = __ldg((const uint2*)(g_feath + (size_t)u * D0) + lane);
        float2 f0 = __half22float2(*(const __half2*)&r.x);
        float2 f1 = __half22float2(*(const __half2*)&r.y);
        acc[0] += f0.x; acc[1] += f0.y; acc[2] += f1.x; acc[3] += f1.y;
    }
    float w = g_inv[dir][node];
    __half2* out = (__half2*)(h1 + (size_t)node * D1 + dir * D0 + lane * 4);
    out[0] = __floats2half2_rn(acc[0] * w, acc[1] * w);
    out[1] = __floats2half2_rn(acc[2] * w, acc[3] * w);
}

// ---------------- hop2: h1 fp16 (D=128) -> h2 fp16 [N,256], MLP-8 ---------
__global__ void __launch_bounds__(256) hop2_kernel(
    const __half* __restrict__ h1, __half* __restrict__ h2, int n)
{
    int gid = blockIdx.x * blockDim.x + threadIdx.x;
    int node = gid >> 4;
    int lane = gid & 15;
    int dir = blockIdx.y;
    if (node >= n) return;
    int start = g_rowptr[dir][node];
    int deg   = g_cnt[dir][node];
    const int* adj = g_adj[dir] + start;
    float acc[8] = {};
    int t = 0;
    for (; t + 8 <= deg; t += 8) {
        int u[8];
        #pragma unroll
        for (int j = 0; j < 8; j++) u[j] = __ldg(&adj[t + j]);
        uint4 rs[8];
        #pragma unroll
        for (int j = 0; j < 8; j++)
            rs[j] = __ldg((const uint4*)(h1 + (size_t)u[j] * D1) + lane);
        #pragma unroll
        for (int m = 0; m < 8; m++) {
            const __half2* h = (const __half2*)&rs[m];
            #pragma unroll
            for (int j = 0; j < 4; j++) {
                float2 f = __half22float2(h[j]);
                acc[2 * j]     += f.x;
                acc[2 * j + 1] += f.y;
            }
        }
    }
    for (; t < deg; t++) {
        int u = __ldg(&adj[t]);
        uint4 r = __ldg((const uint4*)(h1 + (size_t)u * D1) + lane);
        const __half2* h = (const __half2*)&r;
        #pragma unroll
        for (int j = 0; j < 4; j++) {
            float2 f = __half22float2(h[j]);
            acc[2 * j]     += f.x;
            acc[2 * j + 1] += f.y;
        }
    }
    float w = g_inv[dir][node];
    __half2 o[4];
    #pragma unroll
    for (int j = 0; j < 4; j++)
        o[j] = __floats2half2_rn(acc[2 * j] * w, acc[2 * j + 1] * w);
    *(uint4*)(h2 + (size_t)node * D2 + dir * D1 + lane * 8) = *(uint4*)o;
}

// ---------------- fp16 GEMM, double-buffered smem (1 sync / k-tile) -------
__device__ __forceinline__ void mma_f16(float* c, const uint32_t* a,
                                        uint32_t b0, uint32_t b1) {
    asm volatile(
        "mma.sync.aligned.m16n8k16.row.col.f32.f16.f16.f32 "
        "{%0,%1,%2,%3}, {%4,%5,%6,%7}, {%8,%9}, {%0,%1,%2,%3};"
        : "+f"(c[0]), "+f"(c[1]), "+f"(c[2]), "+f"(c[3])
        : "r"(a[0]), "r"(a[1]), "r"(a[2]), "r"(a[3]), "r"(b0), "r"(b1));
}

__global__ void __launch_bounds__(256, 2) gemm_f16_kernel(
    const __half* __restrict__ A, __half* __restrict__ C, int N)
{
    __shared__ uint32_t As[2][128][20];   // 20 KB : conflict-free fragment LDS
    __shared__ uint32_t Bs[2][16][136];   // 17 KB : conflict-free
    int tid = threadIdx.x;
    int warp = tid >> 5, lane = tid & 31;
    int warpRow = warp >> 1;
    int warpCol = warp & 1;
    int g = lane >> 2, q = lane & 3;
    int blockRow = blockIdx.x * 128;
    int blockCol = blockIdx.y * 128;
    float c[2][8][4] = {};

    int arow = tid >> 2;
    int ac4  = tid & 3;
    int bk2  = tid >> 5;
    int bn4  = tid & 31;

    const uint4* Ag = (const uint4*)A;
    const uint4* Bg = (const uint4*)g_Wt2h;
    uint4 bufA[2], bufB[2];
    const uint4 zero4 = make_uint4(0u, 0u, 0u, 0u);

    // tile 0 -> stage 0
    #pragma unroll
    for (int i = 0; i < 2; i++) {
        int row = blockRow + arow + i * 64;
        bufA[i] = (row < N) ? __ldg(Ag + (size_t)row * 32 + ac4) : zero4;
        bufB[i] = __ldg(Bg + (size_t)(bk2 + i * 8) * 64 + (blockCol >> 2) + bn4);
    }
    #pragma unroll
    for (int i = 0; i < 2; i++) {
        *(uint4*)&As[0][arow + i * 64][ac4 * 4] = bufA[i];
        *(uint4*)&Bs[0][bk2 + i * 8][bn4 * 4] = bufB[i];
    }
    __syncthreads();

    for (int kt = 0; kt < 8; kt++) {
        int cur = kt & 1;
        if (kt < 7) {       // issue next tile's global loads early
            #pragma unroll
            for (int i = 0; i < 2; i++) {
                int row = blockRow + arow + i * 64;
                bufA[i] = (row < N) ? __ldg(Ag + (size_t)row * 32 + (kt + 1) * 4 + ac4) : zero4;
                bufB[i] = __ldg(Bg + (size_t)((kt + 1) * 16 + bk2 + i * 8) * 64 + (blockCol >> 2) + bn4);
            }
        }
        #pragma unroll
        for (int ks = 0; ks < 2; ks++) {
            int kb = ks * 8;
            uint32_t a[2][4];
            #pragma unroll
            for (int mt = 0; mt < 2; mt++) {
                int rb = warpRow * 32 + mt * 16;
                a[mt][0] = As[cur][rb + g    ][kb + q    ];
                a[mt][1] = As[cur][rb + g + 8][kb + q    ];
                a[mt][2] = As[cur][rb + g    ][kb + q + 4];
                a[mt][3] = As[cur][rb + g + 8][kb + q + 4];
            }
            #pragma unroll
            for (int nt = 0; nt < 8; nt++) {
                int cb = warpCol * 64 + nt * 8 + g;
                uint32_t b0 = Bs[cur][kb + q    ][cb];
                uint32_t b1 = Bs[cur][kb + q + 4][cb];
                mma_f16(c[0][nt], a[0], b0, b1);
                mma_f16(c[1][nt], a[1], b0, b1);
            }
        }
        if (kt < 7) {       // fill the other stage, single sync per tile
            #pragma unroll
            for (int i = 0; i < 2; i++) {
                *(uint4*)&As[1 - cur][arow + i * 64][ac4 * 4] = bufA[i];
                *(uint4*)&Bs[1 - cur][bk2 + i * 8][bn4 * 4] = bufB[i];
            }
            __syncthreads();
        }
    }

    #pragma unroll
    for (int mt = 0; mt < 2; mt++)
        #pragma unroll
        for (int nt = 0; nt < 8; nt++) {
            int col = blockCol + warpCol * 64 + nt * 8 + q * 2;
            int r0 = blockRow + warpRow * 32 + mt * 16 + g;
            if (r0 < N)
                *(__half2*)(C + (size_t)r0 * D2 + col) =
                    __floats2half2_rn(c[mt][nt][0], c[mt][nt][1]);
            int r1 = r0 + 8;
            if (r1 < N)
                *(__half2*)(C + (size_t)r1 * D2 + col) =
                    __floats2half2_rn(c[mt][nt][2], c[mt][nt][3]);
        }
}

// ---------------- fused hop3: aggregate P fp16, scale, bias, MLP-8 --------
__global__ void __launch_bounds__(256) hop3_kernel(
    const __half* __restrict__ P, const float* __restrict__ bias,
    float* __restrict__ out, int n)
{
    int node = blockIdx.x * 8 + (threadIdx.x >> 5);
    int lane = threadIdx.x & 31;
    if (node >= n) return;
    float aI[4] = {}, aO[4] = {};
    #pragma unroll
    for (int dir = 0; dir < 2; dir++) {
        float* acc = dir ? aO : aI;
        int off = dir ? ODIM : 0;
        int start = g_rowptr[dir][node];
        int deg   = g_cnt[dir][node];
        const int* adj = g_adj[dir] + start;
        int t = 0;
        for (; t + 8 <= deg; t += 8) {
            int u[8];
            #pragma unroll
            for (int j = 0; j < 8; j++) u[j] = __ldg(&adj[t + j]);
            uint2 rs[8];
            #pragma unroll
            for (int j = 0; j < 8; j++)
                rs[j] = __ldg((const uint2*)(P + (size_t)u[j] * D2 + off) + lane);
            #pragma unroll
            for (int j = 0; j < 8; j++) {
                float2 f0 = __half22float2(*(const __half2*)&rs[j].x);
                float2 f1 = __half22float2(*(const __half2*)&rs[j].y);
                acc[0] += f0.x; acc[1] += f0.y; acc[2] += f1.x; acc[3] += f1.y;
            }
        }
        for (; t < deg; t++) {
            int u = __ldg(&adj[t]);
            uint2 r = __ldg((const uint2*)(P + (size_t)u * D2 + off) + lane);
            float2 f0 = __half22float2(*(const __half2*)&r.x);
            float2 f1 = __half22float2(*(const __half2*)&r.y);
            acc[0] += f0.x; acc[1] += f0.y; acc[2] += f1.x; acc[3] += f1.y;
        }
    }
    float wi = g_inv[0][node], wo = g_inv[1][node];
    float4 b = __ldg((const float4*)bias + lane);
    float4 r;
    r.x = aI[0] * wi + aO[0] * wo + b.x;
    r.y = aI[1] * wi + aO[1] * wo + b.y;
    r.z = aI[2] * wi + aO[2] * wo + b.z;
    r.w = aI[3] * wi + aO[3] * wo + b.w;
    ((float4*)(out + (size_t)node * ODIM))[lane] = r;
}

// ---------------- launch ----------------------------------------------------
extern "C" void kernel_launch(void* const* d_in, const int* in_sizes, int n_in,
                              void* d_out, int out_size)
{
    const float* feat  = (const float*)d_in[0];
    const void*  edges = d_in[1];
    const float* W     = (const float*)d_in[2];
    const float* bias  = (const float*)d_in[3];
    float* out = (float*)d_out;

    int N = in_sizes[0] / D0;     // 50000
    int E = in_sizes[1] / 2;      // 800000

    __half *h1, *h2, *P;
    cudaGetSymbolAddress((void**)&h1, g_h1h);
    cudaGetSymbolAddress((void**)&h2, g_h2h);
    cudaGetSymbolAddress((void**)&P,  g_Ph);

    const int T = 256;
    int nfeat2 = N * D0 / 2;
    initA_kernel<<<(nfeat2 + T - 1) / T, T>>>(feat, (const unsigned*)edges, N, nfeat2, E);
    convert_count_kernel<<<(E + T - 1) / T, T>>>(edges, E);

    dim3 sgrid((N + 1023) / 1024, 2);
    scan_fused_kernel<<<sgrid, 1024>>>(W, N);
    fill_kernel<<<(E + T - 1) / T, T>>>(E);

    {
        unsigned total = (unsigned)N * 16;
        dim3 g((total + T - 1) / T, 2);
        hop1_kernel<<<g, T>>>(h1, N);
        hop2_kernel<<<g, T>>>(h1, h2, N);
    }
    {
        dim3 g((N + 127) / 128, 2);
        gemm_f16_kernel<<<g, T>>>(h2, P, N);
    }
    hop3_kernel<<<(N + 7) / 8, T>>>(P, bias, out, N);
}